// round 11
// baseline (speedup 1.0000x reference)
#include <cuda_runtime.h>
#include <cuda_bf16.h>
#include <math.h>
#include <stdint.h>

#define T_SEQ 4096
#define C_DIM 1024
#define NH    16
#define HD    64
#define KDIM  1024

// ---------------- scratch (static device arrays, allowed) ---------------------
__device__ float g_qkv[(size_t)T_SEQ * 3 * C_DIM];
__device__ float g_invf[32];
// GEMM operands (bf16 split, row-major [rows][K])
__device__ __nv_bfloat16 g_Ahi[(size_t)T_SEQ * KDIM];
__device__ __nv_bfloat16 g_Alo[(size_t)T_SEQ * KDIM];
__device__ __nv_bfloat16 g_Bhi[(size_t)3 * C_DIM * KDIM];
__device__ __nv_bfloat16 g_Blo[(size_t)3 * C_DIM * KDIM];
// attention operands (bf16 split)
__device__ __nv_bfloat16 g_Qhi[(size_t)NH * T_SEQ * HD];   // [h][t][d]
__device__ __nv_bfloat16 g_Qlo[(size_t)NH * T_SEQ * HD];
__device__ __nv_bfloat16 g_Khi[(size_t)NH * T_SEQ * HD];
__device__ __nv_bfloat16 g_Klo[(size_t)NH * T_SEQ * HD];
__device__ __nv_bfloat16 g_Vthi[(size_t)NH * HD * T_SEQ];  // [h][d][t]
__device__ __nv_bfloat16 g_Vtlo[(size_t)NH * HD * T_SEQ];

// ---------------- helpers ------------------------------------------------------
__device__ __forceinline__ uint32_t smem_u32(const void* p) {
    uint32_t a;
    asm("{ .reg .u64 t; cvta.to.shared.u64 t, %1; cvt.u32.u64 %0, t; }"
        : "=r"(a) : "l"(p));
    return a;
}
__device__ __forceinline__ void cp16(uint32_t dst, const void* src) {
    asm volatile("cp.async.cg.shared.global [%0], [%1], 16;"
                 :: "r"(dst), "l"(src));
}
#define CP_COMMIT()  asm volatile("cp.async.commit_group;" ::: "memory")
#define CP_WAIT1()   asm volatile("cp.async.wait_group 1;" ::: "memory")
#define CP_WAITALL() asm volatile("cp.async.wait_all;" ::: "memory")

#define LDSM4(r, addr)                                                          \
    asm volatile("ldmatrix.sync.aligned.m8n8.x4.shared.b16 {%0,%1,%2,%3}, [%4];"\
                 : "=r"((r)[0]), "=r"((r)[1]), "=r"((r)[2]), "=r"((r)[3])       \
                 : "r"(addr))

#define MMA16816(c, a, b0, b1)                                                  \
    asm volatile("mma.sync.aligned.m16n8k16.row.col.f32.bf16.bf16.f32 "         \
                 "{%0,%1,%2,%3}, {%4,%5,%6,%7}, {%8,%9}, {%0,%1,%2,%3};"        \
                 : "+f"((c)[0]), "+f"((c)[1]), "+f"((c)[2]), "+f"((c)[3])       \
                 : "r"((a)[0]), "r"((a)[1]), "r"((a)[2]), "r"((a)[3]),          \
                   "r"(b0), "r"(b1))

// swizzle for [rows][64B] tiles (GEMM path)
__device__ __forceinline__ uint32_t swz(uint32_t row, uint32_t kb) {
    return row * 64u + (kb ^ (((row >> 1) & 3u) << 4));
}
// swizzle for [rows][128B] tiles (flash path), c = 16B-chunk index 0..7
__device__ __forceinline__ uint32_t swz128(uint32_t row, uint32_t c) {
    return row * 128u + ((c ^ (row & 7u)) << 4);
}
__device__ __forceinline__ uint32_t packbf(__nv_bfloat16 a, __nv_bfloat16 b) {
    __nv_bfloat162 t;
    t.x = a; t.y = b;
    return *reinterpret_cast<uint32_t*>(&t);
}
// pack truncated-bf16 of (a -> low half, b -> high half) in one PRMT
__device__ __forceinline__ uint32_t prmt_hi(float a, float b) {
    uint32_t r;
    asm("prmt.b32 %0, %1, %2, 0x7632;"
        : "=r"(r) : "r"(__float_as_uint(a)), "r"(__float_as_uint(b)));
    return r;
}
// packed rn cvt: x -> low bf16, y -> high bf16
__device__ __forceinline__ uint32_t cvtbf2(float x, float y) {
    uint32_t r;
    asm("cvt.rn.bf16x2.f32 %0, %1, %2;" : "=r"(r) : "f"(y), "f"(x));
    return r;
}
__device__ __forceinline__ float trunc_res(float p) {
    return p - __uint_as_float(__float_as_uint(p) & 0xFFFF0000u);
}

// ---------------- inv_freq table ----------------------------------------------
__global__ void init_invfreq_kernel() {
    int j = threadIdx.x;
    if (j < 32) {
        double e = (double)(2 * j) / 64.0;
        g_invf[j] = (float)exp(-e * log(10000.0));
    }
}

// ---------------- fp32 -> bf16 hi/lo split (row-major) -------------------------
__global__ void split_kernel(const float* __restrict__ src,
                             __nv_bfloat16* __restrict__ hi,
                             __nv_bfloat16* __restrict__ lo, int total) {
    int idx = blockIdx.x * blockDim.x + threadIdx.x;
    if (idx >= total) return;
    int m = idx >> 7;
    int k0 = (idx & 127) * 8;
    float4 a = *(const float4*)(src + (size_t)m * KDIM + k0);
    float4 b = *(const float4*)(src + (size_t)m * KDIM + k0 + 4);
    float v[8] = {a.x, a.y, a.z, a.w, b.x, b.y, b.z, b.w};
    __nv_bfloat16 h[8], l[8];
#pragma unroll
    for (int j = 0; j < 8; j++) {
        h[j] = __float2bfloat16(v[j]);
        l[j] = __float2bfloat16(v[j] - __bfloat162float(h[j]));
    }
    *(uint4*)(hi + (size_t)m * KDIM + k0) = *(uint4*)h;
    *(uint4*)(lo + (size_t)m * KDIM + k0) = *(uint4*)l;
}

// ---------------- W [K,N] -> Bt [N,K] bf16 hi/lo -------------------------------
__global__ void transpose_split_kernel(const float* __restrict__ W,
                                       __nv_bfloat16* __restrict__ hi,
                                       __nv_bfloat16* __restrict__ lo, int N) {
    __shared__ float s[32][33];
    int n0 = blockIdx.x * 32, k0 = blockIdx.y * 32;
    int t = threadIdx.x;
#pragma unroll
    for (int i = 0; i < 4; i++) {
        int e = t + i * 256;
        int kl = e >> 5, nl = e & 31;
        s[kl][nl] = W[(size_t)(k0 + kl) * N + n0 + nl];
    }
    __syncthreads();
    if (t < 128) {
        int nl = t >> 2, kg = t & 3, kl0 = kg * 8;
        int n = n0 + nl, k = k0 + kl0;
        __nv_bfloat16 h[8], l[8];
#pragma unroll
        for (int j = 0; j < 8; j++) {
            float v = s[kl0 + j][nl];
            h[j] = __float2bfloat16(v);
            l[j] = __float2bfloat16(v - __bfloat162float(h[j]));
        }
        *(uint4*)(hi + (size_t)n * KDIM + k) = *(uint4*)h;
        *(uint4*)(lo + (size_t)n * KDIM + k) = *(uint4*)l;
    }
}

// ---------------- mma.sync dense GEMM (R7 validated: 128x64, BK=32) ------------
#define GBM 128
#define GBN 64
#define GBK 32
#define G_STAGES 3
#define G_STAGE_BYTES 24576   // Ahi 8K | Alo 8K | Bhi 4K | Blo 4K
#define G_SMEM (G_STAGES * G_STAGE_BYTES + 1024)

__global__ __launch_bounds__(256, 2)
void mma_gemm_kernel(const __nv_bfloat16* __restrict__ Ahi,
                     const __nv_bfloat16* __restrict__ Alo,
                     const __nv_bfloat16* __restrict__ Bhi,
                     const __nv_bfloat16* __restrict__ Blo,
                     const float* __restrict__ bias,
                     float* __restrict__ C, int N)
{
    extern __shared__ char sraw[];
    char* smp = (char*)(((uintptr_t)sraw + 1023) & ~(uintptr_t)1023);
    uint32_t sb = smem_u32(smp);

    int tid = threadIdx.x, lane = tid & 31, w = tid >> 5;
    int m0 = blockIdx.y * GBM, n0 = blockIdx.x * GBN;
    int mw = (w >> 1) * 32, nw = (w & 1) * 32;

    const char* gA[2] = {(const char*)(Ahi + (size_t)m0 * KDIM),
                         (const char*)(Alo + (size_t)m0 * KDIM)};
    const char* gB[2] = {(const char*)(Bhi + (size_t)n0 * KDIM),
                         (const char*)(Blo + (size_t)n0 * KDIM)};

    int arow0 = tid >> 2,         akch0 = tid & 3;
    int arow1 = (tid + 256) >> 2, akch1 = tid & 3;
    int brow  = tid >> 2,         bkch  = tid & 3;

    auto load_stage = [&](int kc, int s) {
        uint32_t base = sb + (uint32_t)s * G_STAGE_BYTES;
        size_t gk = (size_t)kc * 64;
#pragma unroll
        for (int h = 0; h < 2; h++) {
            cp16(base + h * 8192 + swz(arow0, akch0 * 16),
                 gA[h] + (size_t)arow0 * (KDIM * 2) + gk + akch0 * 16);
            cp16(base + h * 8192 + swz(arow1, akch1 * 16),
                 gA[h] + (size_t)arow1 * (KDIM * 2) + gk + akch1 * 16);
            cp16(base + 16384 + h * 4096 + swz(brow, bkch * 16),
                 gB[h] + (size_t)brow * (KDIM * 2) + gk + bkch * 16);
        }
        CP_COMMIT();
    };

    float acc[2][4][4];
#pragma unroll
    for (int i = 0; i < 2; i++)
#pragma unroll
        for (int j = 0; j < 4; j++)
#pragma unroll
            for (int k = 0; k < 4; k++) acc[i][j][k] = 0.f;

    const int KITERS = KDIM / GBK;
    load_stage(0, 0);
    load_stage(1, 1);

    for (int kc = 0; kc < KITERS; kc++) {
        CP_WAIT1();
        __syncthreads();
        if (kc + 2 < KITERS) load_stage(kc + 2, (kc + 2) % G_STAGES);
        else CP_COMMIT();

        uint32_t sbase = sb + (uint32_t)(kc % G_STAGES) * G_STAGE_BYTES;
#pragma unroll
        for (int ks = 0; ks < 2; ks++) {
            uint32_t ah[2][4], al[2][4], bh[2][4], bl[2][4];
            int kbA = ks * 32 + ((lane >> 4) << 4);
#pragma unroll
            for (int mt = 0; mt < 2; mt++) {
                int row = mw + mt * 16 + (lane & 7) + (((lane >> 3) & 1) << 3);
                uint32_t a = sbase + swz(row, kbA);
                LDSM4(ah[mt], a);
                LDSM4(al[mt], a + 8192);
            }
            int kbB = ks * 32 + (((lane >> 3) & 1) << 4);
#pragma unroll
            for (int p = 0; p < 2; p++) {
                int row = nw + p * 16 + (lane & 7) + (((lane >> 4) & 1) << 3);
                uint32_t a = sbase + 16384 + swz(row, kbB);
                LDSM4(bh[p], a);
                LDSM4(bl[p], a + 4096);
            }
#pragma unroll
            for (int mt = 0; mt < 2; mt++)
#pragma unroll
                for (int nt = 0; nt < 4; nt++) {
                    int p = nt >> 1, q = (nt & 1) * 2;
                    MMA16816(acc[mt][nt], ah[mt], bh[p][q], bh[p][q + 1]);
                    MMA16816(acc[mt][nt], ah[mt], bl[p][q], bl[p][q + 1]);
                    MMA16816(acc[mt][nt], al[mt], bh[p][q], bh[p][q + 1]);
                }
        }
    }
    CP_WAITALL();

#pragma unroll
    for (int mt = 0; mt < 2; mt++)
#pragma unroll
        for (int nt = 0; nt < 4; nt++) {
            int row = m0 + mw + mt * 16 + (lane >> 2);
            int col = n0 + nw + nt * 8 + 2 * (lane & 3);
            float b0 = bias[col], b1 = bias[col + 1];
            float2 v0 = make_float2(acc[mt][nt][0] + b0, acc[mt][nt][1] + b1);
            float2 v1 = make_float2(acc[mt][nt][2] + b0, acc[mt][nt][3] + b1);
            *(float2*)(C + (size_t)row * N + col)       = v0;
            *(float2*)(C + (size_t)(row + 8) * N + col) = v1;
        }
}

// ---------------- RoPE + bf16 split + head-major / V-transpose -----------------
__device__ __forceinline__ float reduce_2pi(float theta) {
    double k = nearbyint((double)theta * 0.15915494309189535);
    return (float)((double)theta - k * 6.283185307179586);
}

__global__ __launch_bounds__(256)
void rope_qkv_kernel() {
    __shared__ float sV[64][65];
    int h = blockIdx.y, t0 = blockIdx.x * 64, tid = threadIdx.x;

    for (int e = tid; e < 2048; e += 256) {
        int tl = e >> 5, i = e & 31;
        int t = t0 + tl, d0 = 2 * i, d1 = d0 + 1;
        int j0 = (d0 < 32) ? d0 : d0 - 32;
        int j1 = (d1 < 32) ? d1 : d1 - 32;

        float th0 = (float)t * g_invf[j0];
        float th1 = (float)t * g_invf[j1];
        float r0 = reduce_2pi(th0), r1 = reduce_2pi(th1);
        float s0, c0, s1, c1;
        sincosf(r0, &s0, &c0);
        sincosf(r1, &s1, &c1);

        const float* src = g_qkv + (size_t)t * (3 * C_DIM) + h * HD;
        float q0 = src[d0],             q1 = src[d1];
        float k0 = src[C_DIM + d0],     k1 = src[C_DIM + d1];
        float v0 = src[2 * C_DIM + d0], v1 = src[2 * C_DIM + d1];

        float qa = q0 * c0 - q1 * s0, qb = q1 * c1 + q0 * s1;
        float ka = k0 * c0 - k1 * s0, kb = k1 * c1 + k0 * s1;

        __nv_bfloat16 qah = __float2bfloat16(qa);
        __nv_bfloat16 qbh = __float2bfloat16(qb);
        __nv_bfloat16 kah = __float2bfloat16(ka);
        __nv_bfloat16 kbh = __float2bfloat16(kb);
        __nv_bfloat16 qal = __float2bfloat16(qa - __bfloat162float(qah));
        __nv_bfloat16 qbl = __float2bfloat16(qb - __bfloat162float(qbh));
        __nv_bfloat16 kal = __float2bfloat16(ka - __bfloat162float(kah));
        __nv_bfloat16 kbl = __float2bfloat16(kb - __bfloat162float(kbh));

        size_t dst = ((size_t)h * T_SEQ + t) * HD + d0;
        *(uint32_t*)(g_Qhi + dst) = packbf(qah, qbh);
        *(uint32_t*)(g_Qlo + dst) = packbf(qal, qbl);
        *(uint32_t*)(g_Khi + dst) = packbf(kah, kbh);
        *(uint32_t*)(g_Klo + dst) = packbf(kal, kbl);

        sV[tl][d0] = v0;
        sV[tl][d1] = v1;
    }
    __syncthreads();
    for (int e = tid; e < 2048; e += 256) {
        int d = e >> 5, tp = (e & 31) * 2;
        float v0 = sV[tp][d], v1 = sV[tp + 1][d];
        __nv_bfloat16 h0 = __float2bfloat16(v0);
        __nv_bfloat16 h1 = __float2bfloat16(v1);
        __nv_bfloat16 l0 = __float2bfloat16(v0 - __bfloat162float(h0));
        __nv_bfloat16 l1 = __float2bfloat16(v1 - __bfloat162float(h1));
        size_t dst = ((size_t)h * HD + d) * T_SEQ + t0 + tp;
        *(uint32_t*)(g_Vthi + dst) = packbf(h0, h1);
        *(uint32_t*)(g_Vtlo + dst) = packbf(l0, l1);
    }
}

// ---------------- Flash attention, mma.sync bf16-split -------------------------
// Br=128 (8 warps x 16 rows), Bc=64, 3-stage cp.async, single sync per j-tile.
// Softmax exp/pack interleaved with PV MMAs per k-slice.
#define FB_STAGES 3
#define FB_STAGE 32768     // Khi 8K | Klo 8K | Vthi 8K | Vtlo 8K
#define FB_SMEM  (FB_STAGES * FB_STAGE + 1024)

__global__ __launch_bounds__(256, 2)
void flash_mma_kernel() {
    extern __shared__ char sraw[];
    char* smp = (char*)(((uintptr_t)sraw + 127) & ~(uintptr_t)127);
    uint32_t sb = smem_u32(smp);

    int tid = threadIdx.x, lane = tid & 31, w = tid >> 5;
    int h  = blockIdx.y;
    int qt = (int)gridDim.x - 1 - (int)blockIdx.x;
    int wrow = w * 16;
    int qr = lane >> 2, qc2 = 2 * (lane & 3);

    // ---- preload Q fragments (hi/lo) from global ----
    uint32_t aQh[4][4], aQl[4][4];
    {
        const __nv_bfloat16* Qh =
            g_Qhi + ((size_t)h * T_SEQ + qt * 128 + wrow + qr) * HD;
        const __nv_bfloat16* Ql =
            g_Qlo + ((size_t)h * T_SEQ + qt * 128 + wrow + qr) * HD;
#pragma unroll
        for (int ks = 0; ks < 4; ks++) {
            int k0 = ks * 16 + qc2;
            aQh[ks][0] = *(const uint32_t*)(Qh + k0);
            aQh[ks][1] = *(const uint32_t*)(Qh + 8 * HD + k0);
            aQh[ks][2] = *(const uint32_t*)(Qh + k0 + 8);
            aQh[ks][3] = *(const uint32_t*)(Qh + 8 * HD + k0 + 8);
            aQl[ks][0] = *(const uint32_t*)(Ql + k0);
            aQl[ks][1] = *(const uint32_t*)(Ql + 8 * HD + k0);
            aQl[ks][2] = *(const uint32_t*)(Ql + k0 + 8);
            aQl[ks][3] = *(const uint32_t*)(Ql + 8 * HD + k0 + 8);
        }
    }

    float o[8][4];
#pragma unroll
    for (int i = 0; i < 8; i++)
#pragma unroll
        for (int j = 0; j < 4; j++) o[i][j] = 0.f;
    float m0 = -1e30f, m1 = -1e30f, l0 = 0.f, l1 = 0.f;

    int ntiles = 2 * qt + 2;

    int lrow = tid >> 2;       // 0..63
    int lc   = tid & 3;        // chunk 0..3 (+4)
    auto load_stage = [&](int j, int buf) {
        uint32_t base = sb + (uint32_t)buf * FB_STAGE;
        const char* kh = (const char*)g_Khi
            + ((size_t)h * T_SEQ + (size_t)j * 64 + lrow) * (HD * 2);
        const char* kl = (const char*)g_Klo
            + ((size_t)h * T_SEQ + (size_t)j * 64 + lrow) * (HD * 2);
        const char* vh = (const char*)g_Vthi
            + (((size_t)h * HD + lrow) * T_SEQ + (size_t)j * 64) * 2;
        const char* vl = (const char*)g_Vtlo
            + (((size_t)h * HD + lrow) * T_SEQ + (size_t)j * 64) * 2;
#pragma unroll
        for (int cc = lc; cc < 8; cc += 4) {
            uint32_t sw = swz128(lrow, cc);
            cp16(base + sw,         kh + cc * 16);
            cp16(base + 8192  + sw, kl + cc * 16);
            cp16(base + 16384 + sw, vh + cc * 16);
            cp16(base + 24576 + sw, vl + cc * 16);
        }
    };

    load_stage(0, 0);
    CP_COMMIT();
    load_stage(1, 1);
    CP_COMMIT();

    for (int j = 0; j < ntiles; j++) {
        CP_WAIT1();
        __syncthreads();
        // prefetch j+2 into stage (j+2)%3 (safe: all warps are past reads of it)
        if (j + 2 < ntiles) load_stage(j + 2, (j + 2) % FB_STAGES);
        CP_COMMIT();

        uint32_t st  = sb + (uint32_t)(j % FB_STAGES) * FB_STAGE;
        uint32_t sKh = st, sVh = st + 16384;

        // ---- S = Q @ K^T (3-term split) ----
        float s[8][4];
#pragma unroll
        for (int i = 0; i < 8; i++)
#pragma unroll
            for (int jj = 0; jj < 4; jj++) s[i][jj] = 0.f;

        int rsel = (lane & 7) + (((lane >> 4) & 1) << 3);
#pragma unroll
        for (int ks = 0; ks < 4; ks++) {
            int c = 2 * ks + ((lane >> 3) & 1);
#pragma unroll
            for (int p = 0; p < 4; p++) {
                uint32_t bh[4], bl[4];
                int row = p * 16 + rsel;
                uint32_t a = sKh + swz128(row, c);
                LDSM4(bh, a);
                LDSM4(bl, a + 8192);
#pragma unroll
                for (int sub = 0; sub < 2; sub++) {
                    int nt = p * 2 + sub, q = sub * 2;
                    MMA16816(s[nt], aQh[ks], bh[q], bh[q + 1]);
                    MMA16816(s[nt], aQh[ks], bl[q], bl[q + 1]);
                    MMA16816(s[nt], aQl[ks], bh[q], bh[q + 1]);
                }
            }
        }

        // ---- scale + causal mask ----
        int row0 = qt * 128 + wrow + qr;
        bool need_mask = (j >= 2 * qt);
#pragma unroll
        for (int nt = 0; nt < 8; nt++) {
            int cb = j * 64 + nt * 8 + qc2;
#pragma unroll
            for (int e = 0; e < 4; e++) {
                float v = s[nt][e] * 0.125f;
                if (need_mask) {
                    int col = cb + (e & 1);
                    int row = row0 + (e >> 1) * 8;
                    if (col > row) v = -1e30f;
                }
                s[nt][e] = v;
            }
        }

        // ---- row max + rescale factors ----
        float mx0 = -1e30f, mx1 = -1e30f;
#pragma unroll
        for (int nt = 0; nt < 8; nt++) {
            mx0 = fmaxf(mx0, fmaxf(s[nt][0], s[nt][1]));
            mx1 = fmaxf(mx1, fmaxf(s[nt][2], s[nt][3]));
        }
        mx0 = fmaxf(mx0, __shfl_xor_sync(0xffffffffu, mx0, 1));
        mx0 = fmaxf(mx0, __shfl_xor_sync(0xffffffffu, mx0, 2));
        mx1 = fmaxf(mx1, __shfl_xor_sync(0xffffffffu, mx1, 1));
        mx1 = fmaxf(mx1, __shfl_xor_sync(0xffffffffu, mx1, 2));

        float mn0 = fmaxf(m0, mx0), mn1 = fmaxf(m1, mx1);
        float a0 = __expf(m0 - mn0), a1 = __expf(m1 - mn1);
#pragma unroll
        for (int i = 0; i < 8; i++) {
            o[i][0] *= a0; o[i][1] *= a0;
            o[i][2] *= a1; o[i][3] *= a1;
        }

        // ---- interleaved: per k-slice exp + pack + PV MMAs ----
        float sum0 = 0.f, sum1 = 0.f;
#pragma unroll
        for (int ks = 0; ks < 4; ks++) {
            uint32_t ph[4], pl[4];
#pragma unroll
            for (int half = 0; half < 2; half++) {
                int nt = 2 * ks + half;
                float p0 = __expf(s[nt][0] - mn0);
                float p1 = __expf(s[nt][1] - mn0);
                float p2 = __expf(s[nt][2] - mn1);
                float p3 = __expf(s[nt][3] - mn1);
                sum0 += p0 + p1;
                sum1 += p2 + p3;
                ph[half * 2]     = prmt_hi(p0, p1);     // trunc hi pack
                ph[half * 2 + 1] = prmt_hi(p2, p3);
                pl[half * 2]     = cvtbf2(trunc_res(p0), trunc_res(p1));
                pl[half * 2 + 1] = cvtbf2(trunc_res(p2), trunc_res(p3));
            }
            int c = 2 * ks + ((lane >> 3) & 1);
#pragma unroll
            for (int p = 0; p < 4; p++) {
                uint32_t bh[4], bl[4];
                int row = p * 16 + rsel;
                uint32_t a = sVh + swz128(row, c);
                LDSM4(bh, a);
                LDSM4(bl, a + 8192);
#pragma unroll
                for (int sub = 0; sub < 2; sub++) {
                    int nt = p * 2 + sub, q = sub * 2;
                    MMA16816(o[nt], ph, bh[q], bh[q + 1]);
                    MMA16816(o[nt], ph, bl[q], bl[q + 1]);
                    MMA16816(o[nt], pl, bh[q], bh[q + 1]);
                }
            }
        }

        // ---- finish l update ----
        sum0 += __shfl_xor_sync(0xffffffffu, sum0, 1);
        sum0 += __shfl_xor_sync(0xffffffffu, sum0, 2);
        sum1 += __shfl_xor_sync(0xffffffffu, sum1, 1);
        sum1 += __shfl_xor_sync(0xffffffffu, sum1, 2);
        l0 = l0 * a0 + sum0;
        l1 = l1 * a1 + sum1;
        m0 = mn0; m1 = mn1;
    }

    // ---- epilogue: O/l, split to bf16 hi/lo for GEMM2 ----
    float li0 = 1.f / l0, li1 = 1.f / l1;
    int r0 = qt * 128 + wrow + qr;
#pragma unroll
    for (int nt = 0; nt < 8; nt++) {
        int gcol = h * HD + nt * 8 + qc2;
        float f0 = o[nt][0] * li0, f1 = o[nt][1] * li0;
        float f2 = o[nt][2] * li1, f3 = o[nt][3] * li1;
        __nv_bfloat16 h0 = __float2bfloat16(f0);
        __nv_bfloat16 h1 = __float2bfloat16(f1);
        __nv_bfloat16 h2 = __float2bfloat16(f2);
        __nv_bfloat16 h3 = __float2bfloat16(f3);
        size_t o0 = (size_t)r0 * KDIM + gcol;
        size_t o1 = (size_t)(r0 + 8) * KDIM + gcol;
        *(uint32_t*)(g_Ahi + o0) = packbf(h0, h1);
        *(uint32_t*)(g_Alo + o0) = packbf(
            __float2bfloat16(f0 - __bfloat162float(h0)),
            __float2bfloat16(f1 - __bfloat162float(h1)));
        *(uint32_t*)(g_Ahi + o1) = packbf(h2, h3);
        *(uint32_t*)(g_Alo + o1) = packbf(
            __float2bfloat16(f2 - __bfloat162float(h2)),
            __float2bfloat16(f3 - __bfloat162float(h3)));
    }
}

// ---------------- launch ------------------------------------------------------
extern "C" void kernel_launch(void* const* d_in, const int* in_sizes, int n_in,
                              void* d_out, int out_size)
{
    const float* x     = (const float*)d_in[0];
    const float* Wqkv  = (const float*)d_in[1];
    const float* bqkv  = (const float*)d_in[2];
    const float* Wproj = (const float*)d_in[3];
    const float* bproj = (const float*)d_in[4];
    float* out = (float*)d_out;

    float* qkv_p;
    __nv_bfloat16 *ahi, *alo, *bhi, *blo;
    cudaGetSymbolAddress((void**)&qkv_p, g_qkv);
    cudaGetSymbolAddress((void**)&ahi, g_Ahi);
    cudaGetSymbolAddress((void**)&alo, g_Alo);
    cudaGetSymbolAddress((void**)&bhi, g_Bhi);
    cudaGetSymbolAddress((void**)&blo, g_Blo);

    cudaFuncSetAttribute(mma_gemm_kernel,
                         cudaFuncAttributeMaxDynamicSharedMemorySize, G_SMEM);
    cudaFuncSetAttribute(flash_mma_kernel,
                         cudaFuncAttributeMaxDynamicSharedMemorySize, FB_SMEM);

    init_invfreq_kernel<<<1, 32>>>();

    // ---- GEMM1: qkv = x @ Wqkv + bqkv ----
    split_kernel<<<(T_SEQ * (KDIM / 8)) / 256, 256>>>(x, ahi, alo,
                                                      T_SEQ * (KDIM / 8));
    transpose_split_kernel<<<dim3(3 * C_DIM / 32, KDIM / 32), 256>>>(
        Wqkv, bhi, blo, 3 * C_DIM);
    mma_gemm_kernel<<<dim3(3 * C_DIM / GBN, T_SEQ / GBM), 256, G_SMEM>>>(
        ahi, alo, bhi, blo, bqkv, qkv_p, 3 * C_DIM);

    // ---- RoPE + bf16 split + V transpose ----
    rope_qkv_kernel<<<dim3(T_SEQ / 64, NH), 256>>>();

    // ---- flash attention (epilogue writes GEMM2's A operand) ----
    flash_mma_kernel<<<dim3(T_SEQ / 128, NH), 256, FB_SMEM>>>();

    // ---- GEMM2: out = y @ Wproj + bproj ----
    transpose_split_kernel<<<dim3(C_DIM / 32, KDIM / 32), 256>>>(
        Wproj, bhi, blo, C_DIM);
    mma_gemm_kernel<<<dim3(C_DIM / GBN, T_SEQ / GBM), 256, G_SMEM>>>(
        ahi, alo, bhi, blo, bproj, out, C_DIM);
}

// round 13
// speedup vs baseline: 1.5529x; 1.5529x over previous
#include <cuda_runtime.h>
#include <cuda_bf16.h>
#include <math.h>
#include <stdint.h>

#define T_SEQ 4096
#define C_DIM 1024
#define NH    16
#define HD    64
#define KDIM  1024

// ---------------- scratch (static device arrays, allowed) ---------------------
__device__ float g_qkv[(size_t)T_SEQ * 3 * C_DIM];
__device__ float g_invf[32];
// GEMM operands (bf16 split, row-major [rows][K])
__device__ __nv_bfloat16 g_Ahi[(size_t)T_SEQ * KDIM];
__device__ __nv_bfloat16 g_Alo[(size_t)T_SEQ * KDIM];
__device__ __nv_bfloat16 g_Bhi[(size_t)3 * C_DIM * KDIM];
__device__ __nv_bfloat16 g_Blo[(size_t)3 * C_DIM * KDIM];
// attention operands (bf16 split)
__device__ __nv_bfloat16 g_Qhi[(size_t)NH * T_SEQ * HD];   // [h][t][d]
__device__ __nv_bfloat16 g_Qlo[(size_t)NH * T_SEQ * HD];
__device__ __nv_bfloat16 g_Khi[(size_t)NH * T_SEQ * HD];
__device__ __nv_bfloat16 g_Klo[(size_t)NH * T_SEQ * HD];
__device__ __nv_bfloat16 g_Vthi[(size_t)NH * HD * T_SEQ];  // [h][d][t]
__device__ __nv_bfloat16 g_Vtlo[(size_t)NH * HD * T_SEQ];

// ---------------- helpers ------------------------------------------------------
__device__ __forceinline__ uint32_t smem_u32(const void* p) {
    uint32_t a;
    asm("{ .reg .u64 t; cvta.to.shared.u64 t, %1; cvt.u32.u64 %0, t; }"
        : "=r"(a) : "l"(p));
    return a;
}
__device__ __forceinline__ void cp16(uint32_t dst, const void* src) {
    asm volatile("cp.async.cg.shared.global [%0], [%1], 16;"
                 :: "r"(dst), "l"(src));
}
#define CP_COMMIT()  asm volatile("cp.async.commit_group;" ::: "memory")
#define CP_WAIT1()   asm volatile("cp.async.wait_group 1;" ::: "memory")
#define CP_WAITALL() asm volatile("cp.async.wait_all;" ::: "memory")

#define LDSM4(r, addr)                                                          \
    asm volatile("ldmatrix.sync.aligned.m8n8.x4.shared.b16 {%0,%1,%2,%3}, [%4];"\
                 : "=r"((r)[0]), "=r"((r)[1]), "=r"((r)[2]), "=r"((r)[3])       \
                 : "r"(addr))

#define MMA16816(c, a, b0, b1)                                                  \
    asm volatile("mma.sync.aligned.m16n8k16.row.col.f32.bf16.bf16.f32 "         \
                 "{%0,%1,%2,%3}, {%4,%5,%6,%7}, {%8,%9}, {%0,%1,%2,%3};"        \
                 : "+f"((c)[0]), "+f"((c)[1]), "+f"((c)[2]), "+f"((c)[3])       \
                 : "r"((a)[0]), "r"((a)[1]), "r"((a)[2]), "r"((a)[3]),          \
                   "r"(b0), "r"(b1))

// swizzle for [rows][64B] tiles (GEMM path)
__device__ __forceinline__ uint32_t swz(uint32_t row, uint32_t kb) {
    return row * 64u + (kb ^ (((row >> 1) & 3u) << 4));
}
// swizzle for [rows][128B] tiles (flash path), c = 16B-chunk index 0..7
__device__ __forceinline__ uint32_t swz128(uint32_t row, uint32_t c) {
    return row * 128u + ((c ^ (row & 7u)) << 4);
}
__device__ __forceinline__ uint32_t packbf(__nv_bfloat16 a, __nv_bfloat16 b) {
    __nv_bfloat162 t;
    t.x = a; t.y = b;
    return *reinterpret_cast<uint32_t*>(&t);
}
// pack truncated-bf16 of (a -> low half, b -> high half) in one PRMT
__device__ __forceinline__ uint32_t prmt_hi(float a, float b) {
    uint32_t r;
    asm("prmt.b32 %0, %1, %2, 0x7632;"
        : "=r"(r) : "r"(__float_as_uint(a)), "r"(__float_as_uint(b)));
    return r;
}
// packed rn cvt: x -> low bf16, y -> high bf16
__device__ __forceinline__ uint32_t cvtbf2(float x, float y) {
    uint32_t r;
    asm("cvt.rn.bf16x2.f32 %0, %1, %2;" : "=r"(r) : "f"(y), "f"(x));
    return r;
}
__device__ __forceinline__ float trunc_res(float p) {
    return p - __uint_as_float(__float_as_uint(p) & 0xFFFF0000u);
}

// ---------------- inv_freq table ----------------------------------------------
__global__ void init_invfreq_kernel() {
    int j = threadIdx.x;
    if (j < 32) {
        double e = (double)(2 * j) / 64.0;
        g_invf[j] = (float)exp(-e * log(10000.0));
    }
}

// ---------------- fp32 -> bf16 hi/lo split (row-major) -------------------------
__global__ void split_kernel(const float* __restrict__ src,
                             __nv_bfloat16* __restrict__ hi,
                             __nv_bfloat16* __restrict__ lo, int total) {
    int idx = blockIdx.x * blockDim.x + threadIdx.x;
    if (idx >= total) return;
    int m = idx >> 7;
    int k0 = (idx & 127) * 8;
    float4 a = *(const float4*)(src + (size_t)m * KDIM + k0);
    float4 b = *(const float4*)(src + (size_t)m * KDIM + k0 + 4);
    float v[8] = {a.x, a.y, a.z, a.w, b.x, b.y, b.z, b.w};
    __nv_bfloat16 h[8], l[8];
#pragma unroll
    for (int j = 0; j < 8; j++) {
        h[j] = __float2bfloat16(v[j]);
        l[j] = __float2bfloat16(v[j] - __bfloat162float(h[j]));
    }
    *(uint4*)(hi + (size_t)m * KDIM + k0) = *(uint4*)h;
    *(uint4*)(lo + (size_t)m * KDIM + k0) = *(uint4*)l;
}

// ---------------- W [K,N] -> Bt [N,K] bf16 hi/lo -------------------------------
__global__ void transpose_split_kernel(const float* __restrict__ W,
                                       __nv_bfloat16* __restrict__ hi,
                                       __nv_bfloat16* __restrict__ lo, int N) {
    __shared__ float s[32][33];
    int n0 = blockIdx.x * 32, k0 = blockIdx.y * 32;
    int t = threadIdx.x;
#pragma unroll
    for (int i = 0; i < 4; i++) {
        int e = t + i * 256;
        int kl = e >> 5, nl = e & 31;
        s[kl][nl] = W[(size_t)(k0 + kl) * N + n0 + nl];
    }
    __syncthreads();
    if (t < 128) {
        int nl = t >> 2, kg = t & 3, kl0 = kg * 8;
        int n = n0 + nl, k = k0 + kl0;
        __nv_bfloat16 h[8], l[8];
#pragma unroll
        for (int j = 0; j < 8; j++) {
            float v = s[kl0 + j][nl];
            h[j] = __float2bfloat16(v);
            l[j] = __float2bfloat16(v - __bfloat162float(h[j]));
        }
        *(uint4*)(hi + (size_t)n * KDIM + k) = *(uint4*)h;
        *(uint4*)(lo + (size_t)n * KDIM + k) = *(uint4*)l;
    }
}

// ---------------- mma.sync dense GEMM (R7 validated: 128x64, BK=32) ------------
#define GBM 128
#define GBN 64
#define GBK 32
#define G_STAGES 3
#define G_STAGE_BYTES 24576   // Ahi 8K | Alo 8K | Bhi 4K | Blo 4K
#define G_SMEM (G_STAGES * G_STAGE_BYTES + 1024)

__global__ __launch_bounds__(256, 2)
void mma_gemm_kernel(const __nv_bfloat16* __restrict__ Ahi,
                     const __nv_bfloat16* __restrict__ Alo,
                     const __nv_bfloat16* __restrict__ Bhi,
                     const __nv_bfloat16* __restrict__ Blo,
                     const float* __restrict__ bias,
                     float* __restrict__ C, int N)
{
    extern __shared__ char sraw[];
    char* smp = (char*)(((uintptr_t)sraw + 1023) & ~(uintptr_t)1023);
    uint32_t sb = smem_u32(smp);

    int tid = threadIdx.x, lane = tid & 31, w = tid >> 5;
    int m0 = blockIdx.y * GBM, n0 = blockIdx.x * GBN;
    int mw = (w >> 1) * 32, nw = (w & 1) * 32;

    const char* gA[2] = {(const char*)(Ahi + (size_t)m0 * KDIM),
                         (const char*)(Alo + (size_t)m0 * KDIM)};
    const char* gB[2] = {(const char*)(Bhi + (size_t)n0 * KDIM),
                         (const char*)(Blo + (size_t)n0 * KDIM)};

    int arow0 = tid >> 2,         akch0 = tid & 3;
    int arow1 = (tid + 256) >> 2, akch1 = tid & 3;
    int brow  = tid >> 2,         bkch  = tid & 3;

    auto load_stage = [&](int kc, int s) {
        uint32_t base = sb + (uint32_t)s * G_STAGE_BYTES;
        size_t gk = (size_t)kc * 64;
#pragma unroll
        for (int h = 0; h < 2; h++) {
            cp16(base + h * 8192 + swz(arow0, akch0 * 16),
                 gA[h] + (size_t)arow0 * (KDIM * 2) + gk + akch0 * 16);
            cp16(base + h * 8192 + swz(arow1, akch1 * 16),
                 gA[h] + (size_t)arow1 * (KDIM * 2) + gk + akch1 * 16);
            cp16(base + 16384 + h * 4096 + swz(brow, bkch * 16),
                 gB[h] + (size_t)brow * (KDIM * 2) + gk + bkch * 16);
        }
        CP_COMMIT();
    };

    float acc[2][4][4];
#pragma unroll
    for (int i = 0; i < 2; i++)
#pragma unroll
        for (int j = 0; j < 4; j++)
#pragma unroll
            for (int k = 0; k < 4; k++) acc[i][j][k] = 0.f;

    const int KITERS = KDIM / GBK;
    load_stage(0, 0);
    load_stage(1, 1);

    for (int kc = 0; kc < KITERS; kc++) {
        CP_WAIT1();
        __syncthreads();
        if (kc + 2 < KITERS) load_stage(kc + 2, (kc + 2) % G_STAGES);
        else CP_COMMIT();

        uint32_t sbase = sb + (uint32_t)(kc % G_STAGES) * G_STAGE_BYTES;
#pragma unroll
        for (int ks = 0; ks < 2; ks++) {
            uint32_t ah[2][4], al[2][4], bh[2][4], bl[2][4];
            int kbA = ks * 32 + ((lane >> 4) << 4);
#pragma unroll
            for (int mt = 0; mt < 2; mt++) {
                int row = mw + mt * 16 + (lane & 7) + (((lane >> 3) & 1) << 3);
                uint32_t a = sbase + swz(row, kbA);
                LDSM4(ah[mt], a);
                LDSM4(al[mt], a + 8192);
            }
            int kbB = ks * 32 + (((lane >> 3) & 1) << 4);
#pragma unroll
            for (int p = 0; p < 2; p++) {
                int row = nw + p * 16 + (lane & 7) + (((lane >> 4) & 1) << 3);
                uint32_t a = sbase + 16384 + swz(row, kbB);
                LDSM4(bh[p], a);
                LDSM4(bl[p], a + 4096);
            }
#pragma unroll
            for (int mt = 0; mt < 2; mt++)
#pragma unroll
                for (int nt = 0; nt < 4; nt++) {
                    int p = nt >> 1, q = (nt & 1) * 2;
                    MMA16816(acc[mt][nt], ah[mt], bh[p][q], bh[p][q + 1]);
                    MMA16816(acc[mt][nt], ah[mt], bl[p][q], bl[p][q + 1]);
                    MMA16816(acc[mt][nt], al[mt], bh[p][q], bh[p][q + 1]);
                }
        }
    }
    CP_WAITALL();

#pragma unroll
    for (int mt = 0; mt < 2; mt++)
#pragma unroll
        for (int nt = 0; nt < 4; nt++) {
            int row = m0 + mw + mt * 16 + (lane >> 2);
            int col = n0 + nw + nt * 8 + 2 * (lane & 3);
            float b0 = bias[col], b1 = bias[col + 1];
            float2 v0 = make_float2(acc[mt][nt][0] + b0, acc[mt][nt][1] + b1);
            float2 v1 = make_float2(acc[mt][nt][2] + b0, acc[mt][nt][3] + b1);
            *(float2*)(C + (size_t)row * N + col)       = v0;
            *(float2*)(C + (size_t)(row + 8) * N + col) = v1;
        }
}

// ---------------- RoPE + bf16 split + head-major / V-transpose -----------------
__device__ __forceinline__ float reduce_2pi(float theta) {
    double k = nearbyint((double)theta * 0.15915494309189535);
    return (float)((double)theta - k * 6.283185307179586);
}

__global__ __launch_bounds__(256)
void rope_qkv_kernel() {
    __shared__ float sV[64][65];
    int h = blockIdx.y, t0 = blockIdx.x * 64, tid = threadIdx.x;

    for (int e = tid; e < 2048; e += 256) {
        int tl = e >> 5, i = e & 31;
        int t = t0 + tl, d0 = 2 * i, d1 = d0 + 1;
        int j0 = (d0 < 32) ? d0 : d0 - 32;
        int j1 = (d1 < 32) ? d1 : d1 - 32;

        float th0 = (float)t * g_invf[j0];
        float th1 = (float)t * g_invf[j1];
        float r0 = reduce_2pi(th0), r1 = reduce_2pi(th1);
        float s0, c0, s1, c1;
        sincosf(r0, &s0, &c0);
        sincosf(r1, &s1, &c1);

        const float* src = g_qkv + (size_t)t * (3 * C_DIM) + h * HD;
        float q0 = src[d0],             q1 = src[d1];
        float k0 = src[C_DIM + d0],     k1 = src[C_DIM + d1];
        float v0 = src[2 * C_DIM + d0], v1 = src[2 * C_DIM + d1];

        float qa = q0 * c0 - q1 * s0, qb = q1 * c1 + q0 * s1;
        float ka = k0 * c0 - k1 * s0, kb = k1 * c1 + k0 * s1;

        __nv_bfloat16 qah = __float2bfloat16(qa);
        __nv_bfloat16 qbh = __float2bfloat16(qb);
        __nv_bfloat16 kah = __float2bfloat16(ka);
        __nv_bfloat16 kbh = __float2bfloat16(kb);
        __nv_bfloat16 qal = __float2bfloat16(qa - __bfloat162float(qah));
        __nv_bfloat16 qbl = __float2bfloat16(qb - __bfloat162float(qbh));
        __nv_bfloat16 kal = __float2bfloat16(ka - __bfloat162float(kah));
        __nv_bfloat16 kbl = __float2bfloat16(kb - __bfloat162float(kbh));

        size_t dst = ((size_t)h * T_SEQ + t) * HD + d0;
        *(uint32_t*)(g_Qhi + dst) = packbf(qah, qbh);
        *(uint32_t*)(g_Qlo + dst) = packbf(qal, qbl);
        *(uint32_t*)(g_Khi + dst) = packbf(kah, kbh);
        *(uint32_t*)(g_Klo + dst) = packbf(kal, kbl);

        sV[tl][d0] = v0;
        sV[tl][d1] = v1;
    }
    __syncthreads();
    for (int e = tid; e < 2048; e += 256) {
        int d = e >> 5, tp = (e & 31) * 2;
        float v0 = sV[tp][d], v1 = sV[tp + 1][d];
        __nv_bfloat16 h0 = __float2bfloat16(v0);
        __nv_bfloat16 h1 = __float2bfloat16(v1);
        __nv_bfloat16 l0 = __float2bfloat16(v0 - __bfloat162float(h0));
        __nv_bfloat16 l1 = __float2bfloat16(v1 - __bfloat162float(h1));
        size_t dst = ((size_t)h * HD + d) * T_SEQ + t0 + tp;
        *(uint32_t*)(g_Vthi + dst) = packbf(h0, h1);
        *(uint32_t*)(g_Vtlo + dst) = packbf(l0, l1);
    }
}

// ---------------- Flash attention, mma.sync bf16-split (R10 structure) ---------
// Br=128 (8 warps x 16 rows), Bc=64, 2-stage cp.async K/Vt tiles.
// Epilogue writes hi/lo bf16 split of O directly into g_Ahi/g_Alo for GEMM2.
#define FB_STAGE 32768     // Khi 8K | Klo 8K | Vthi 8K | Vtlo 8K
#define FB_SMEM  (2 * FB_STAGE + 1024)

__global__ __launch_bounds__(256, 2)
void flash_mma_kernel() {
    extern __shared__ char sraw[];
    char* smp = (char*)(((uintptr_t)sraw + 127) & ~(uintptr_t)127);
    uint32_t sb = smem_u32(smp);

    int tid = threadIdx.x, lane = tid & 31, w = tid >> 5;
    int h  = blockIdx.y;
    int qt = (int)gridDim.x - 1 - (int)blockIdx.x;
    int wrow = w * 16;
    int qr = lane >> 2, qc2 = 2 * (lane & 3);

    // ---- preload Q fragments (hi/lo) from global ----
    uint32_t aQh[4][4], aQl[4][4];
    {
        const __nv_bfloat16* Qh =
            g_Qhi + ((size_t)h * T_SEQ + qt * 128 + wrow + qr) * HD;
        const __nv_bfloat16* Ql =
            g_Qlo + ((size_t)h * T_SEQ + qt * 128 + wrow + qr) * HD;
#pragma unroll
        for (int ks = 0; ks < 4; ks++) {
            int k0 = ks * 16 + qc2;
            aQh[ks][0] = *(const uint32_t*)(Qh + k0);
            aQh[ks][1] = *(const uint32_t*)(Qh + 8 * HD + k0);
            aQh[ks][2] = *(const uint32_t*)(Qh + k0 + 8);
            aQh[ks][3] = *(const uint32_t*)(Qh + 8 * HD + k0 + 8);
            aQl[ks][0] = *(const uint32_t*)(Ql + k0);
            aQl[ks][1] = *(const uint32_t*)(Ql + 8 * HD + k0);
            aQl[ks][2] = *(const uint32_t*)(Ql + k0 + 8);
            aQl[ks][3] = *(const uint32_t*)(Ql + 8 * HD + k0 + 8);
        }
    }

    float o[8][4];
#pragma unroll
    for (int i = 0; i < 8; i++)
#pragma unroll
        for (int j = 0; j < 4; j++) o[i][j] = 0.f;
    float m0 = -1e30f, m1 = -1e30f, l0 = 0.f, l1 = 0.f;

    int ntiles = 2 * qt + 2;

    int lrow = tid >> 2;       // 0..63
    int lc   = tid & 3;        // chunk 0..3 (+4)
    auto load_stage = [&](int j, int buf) {
        uint32_t base = sb + (uint32_t)buf * FB_STAGE;
        const char* kh = (const char*)g_Khi
            + ((size_t)h * T_SEQ + (size_t)j * 64 + lrow) * (HD * 2);
        const char* kl = (const char*)g_Klo
            + ((size_t)h * T_SEQ + (size_t)j * 64 + lrow) * (HD * 2);
        const char* vh = (const char*)g_Vthi
            + (((size_t)h * HD + lrow) * T_SEQ + (size_t)j * 64) * 2;
        const char* vl = (const char*)g_Vtlo
            + (((size_t)h * HD + lrow) * T_SEQ + (size_t)j * 64) * 2;
#pragma unroll
        for (int cc = lc; cc < 8; cc += 4) {
            uint32_t sw = swz128(lrow, cc);
            cp16(base + sw,         kh + cc * 16);
            cp16(base + 8192  + sw, kl + cc * 16);
            cp16(base + 16384 + sw, vh + cc * 16);
            cp16(base + 24576 + sw, vl + cc * 16);
        }
    };

    load_stage(0, 0);
    CP_COMMIT();

    for (int j = 0; j < ntiles; j++) {
        if (j + 1 < ntiles) load_stage(j + 1, (j + 1) & 1);
        CP_COMMIT();
        CP_WAIT1();
        __syncthreads();

        uint32_t st  = sb + (uint32_t)(j & 1) * FB_STAGE;
        uint32_t sKh = st, sVh = st + 16384;

        // ---- S = Q @ K^T (3-term split) ----
        float s[8][4];
#pragma unroll
        for (int i = 0; i < 8; i++)
#pragma unroll
            for (int jj = 0; jj < 4; jj++) s[i][jj] = 0.f;

#pragma unroll
        for (int ks = 0; ks < 4; ks++) {
            int rsel = (lane & 7) + (((lane >> 4) & 1) << 3);
            int c    = 2 * ks + ((lane >> 3) & 1);
#pragma unroll
            for (int p = 0; p < 4; p++) {
                uint32_t bh[4], bl[4];
                int row = p * 16 + rsel;
                uint32_t a = sKh + swz128(row, c);
                LDSM4(bh, a);
                LDSM4(bl, a + 8192);
#pragma unroll
                for (int sub = 0; sub < 2; sub++) {
                    int nt = p * 2 + sub, q = sub * 2;
                    MMA16816(s[nt], aQh[ks], bh[q], bh[q + 1]);
                    MMA16816(s[nt], aQh[ks], bl[q], bl[q + 1]);
                    MMA16816(s[nt], aQl[ks], bh[q], bh[q + 1]);
                }
            }
        }

        // ---- scale + causal mask ----
        int row0 = qt * 128 + wrow + qr;
        bool need_mask = (j >= 2 * qt);
#pragma unroll
        for (int nt = 0; nt < 8; nt++) {
            int cb = j * 64 + nt * 8 + qc2;
#pragma unroll
            for (int e = 0; e < 4; e++) {
                float v = s[nt][e] * 0.125f;
                if (need_mask) {
                    int col = cb + (e & 1);
                    int row = row0 + (e >> 1) * 8;
                    if (col > row) v = -1e30f;
                }
                s[nt][e] = v;
            }
        }

        // ---- online softmax on fragments ----
        float mx0 = -1e30f, mx1 = -1e30f;
#pragma unroll
        for (int nt = 0; nt < 8; nt++) {
            mx0 = fmaxf(mx0, fmaxf(s[nt][0], s[nt][1]));
            mx1 = fmaxf(mx1, fmaxf(s[nt][2], s[nt][3]));
        }
        mx0 = fmaxf(mx0, __shfl_xor_sync(0xffffffffu, mx0, 1));
        mx0 = fmaxf(mx0, __shfl_xor_sync(0xffffffffu, mx0, 2));
        mx1 = fmaxf(mx1, __shfl_xor_sync(0xffffffffu, mx1, 1));
        mx1 = fmaxf(mx1, __shfl_xor_sync(0xffffffffu, mx1, 2));

        float mn0 = fmaxf(m0, mx0), mn1 = fmaxf(m1, mx1);
        float a0 = __expf(m0 - mn0), a1 = __expf(m1 - mn1);
        float sum0 = 0.f, sum1 = 0.f;
#pragma unroll
        for (int nt = 0; nt < 8; nt++) {
            float p0 = __expf(s[nt][0] - mn0);
            float p1 = __expf(s[nt][1] - mn0);
            float p2 = __expf(s[nt][2] - mn1);
            float p3 = __expf(s[nt][3] - mn1);
            s[nt][0] = p0; s[nt][1] = p1; s[nt][2] = p2; s[nt][3] = p3;
            sum0 += p0 + p1;
            sum1 += p2 + p3;
        }
        sum0 += __shfl_xor_sync(0xffffffffu, sum0, 1);
        sum0 += __shfl_xor_sync(0xffffffffu, sum0, 2);
        sum1 += __shfl_xor_sync(0xffffffffu, sum1, 1);
        sum1 += __shfl_xor_sync(0xffffffffu, sum1, 2);
        l0 = l0 * a0 + sum0;
        l1 = l1 * a1 + sum1;
        m0 = mn0; m1 = mn1;
#pragma unroll
        for (int i = 0; i < 8; i++) {
            o[i][0] *= a0; o[i][1] *= a0;
            o[i][2] *= a1; o[i][3] *= a1;
        }

        // ---- repack P -> A fragments (cheap truncation split) ----
        uint32_t aPh[4][4], aPl[4][4];
#pragma unroll
        for (int ks = 0; ks < 4; ks++) {
#pragma unroll
            for (int half = 0; half < 2; half++) {
                int nt = 2 * ks + half;
                aPh[ks][half * 2]     = prmt_hi(s[nt][0], s[nt][1]);
                aPh[ks][half * 2 + 1] = prmt_hi(s[nt][2], s[nt][3]);
                aPl[ks][half * 2]     = cvtbf2(trunc_res(s[nt][0]),
                                               trunc_res(s[nt][1]));
                aPl[ks][half * 2 + 1] = cvtbf2(trunc_res(s[nt][2]),
                                               trunc_res(s[nt][3]));
            }
        }

        // ---- O += P @ V (3-term split) ----
#pragma unroll
        for (int ks = 0; ks < 4; ks++) {
            int rsel = (lane & 7) + (((lane >> 4) & 1) << 3);
            int c    = 2 * ks + ((lane >> 3) & 1);
#pragma unroll
            for (int p = 0; p < 4; p++) {
                uint32_t bh[4], bl[4];
                int row = p * 16 + rsel;
                uint32_t a = sVh + swz128(row, c);
                LDSM4(bh, a);
                LDSM4(bl, a + 8192);
#pragma unroll
                for (int sub = 0; sub < 2; sub++) {
                    int nt = p * 2 + sub, q = sub * 2;
                    MMA16816(o[nt], aPh[ks], bh[q], bh[q + 1]);
                    MMA16816(o[nt], aPh[ks], bl[q], bl[q + 1]);
                    MMA16816(o[nt], aPl[ks], bh[q], bh[q + 1]);
                }
            }
        }
        __syncthreads();
    }

    // ---- epilogue: O/l, split to bf16 hi/lo for GEMM2 ----
    float li0 = 1.f / l0, li1 = 1.f / l1;
    int r0 = qt * 128 + wrow + qr;
#pragma unroll
    for (int nt = 0; nt < 8; nt++) {
        int gcol = h * HD + nt * 8 + qc2;
        float f0 = o[nt][0] * li0, f1 = o[nt][1] * li0;
        float f2 = o[nt][2] * li1, f3 = o[nt][3] * li1;
        __nv_bfloat16 h0 = __float2bfloat16(f0);
        __nv_bfloat16 h1 = __float2bfloat16(f1);
        __nv_bfloat16 h2 = __float2bfloat16(f2);
        __nv_bfloat16 h3 = __float2bfloat16(f3);
        size_t o0 = (size_t)r0 * KDIM + gcol;
        size_t o1 = (size_t)(r0 + 8) * KDIM + gcol;
        *(uint32_t*)(g_Ahi + o0) = packbf(h0, h1);
        *(uint32_t*)(g_Alo + o0) = packbf(
            __float2bfloat16(f0 - __bfloat162float(h0)),
            __float2bfloat16(f1 - __bfloat162float(h1)));
        *(uint32_t*)(g_Ahi + o1) = packbf(h2, h3);
        *(uint32_t*)(g_Alo + o1) = packbf(
            __float2bfloat16(f2 - __bfloat162float(h2)),
            __float2bfloat16(f3 - __bfloat162float(h3)));
    }
}

// ---------------- launch ------------------------------------------------------
extern "C" void kernel_launch(void* const* d_in, const int* in_sizes, int n_in,
                              void* d_out, int out_size)
{
    const float* x     = (const float*)d_in[0];
    const float* Wqkv  = (const float*)d_in[1];
    const float* bqkv  = (const float*)d_in[2];
    const float* Wproj = (const float*)d_in[3];
    const float* bproj = (const float*)d_in[4];
    float* out = (float*)d_out;

    float* qkv_p;
    __nv_bfloat16 *ahi, *alo, *bhi, *blo;
    cudaGetSymbolAddress((void**)&qkv_p, g_qkv);
    cudaGetSymbolAddress((void**)&ahi, g_Ahi);
    cudaGetSymbolAddress((void**)&alo, g_Alo);
    cudaGetSymbolAddress((void**)&bhi, g_Bhi);
    cudaGetSymbolAddress((void**)&blo, g_Blo);

    cudaFuncSetAttribute(mma_gemm_kernel,
                         cudaFuncAttributeMaxDynamicSharedMemorySize, G_SMEM);
    cudaFuncSetAttribute(flash_mma_kernel,
                         cudaFuncAttributeMaxDynamicSharedMemorySize, FB_SMEM);

    init_invfreq_kernel<<<1, 32>>>();

    // ---- GEMM1: qkv = x @ Wqkv + bqkv ----
    split_kernel<<<(T_SEQ * (KDIM / 8)) / 256, 256>>>(x, ahi, alo,
                                                      T_SEQ * (KDIM / 8));
    transpose_split_kernel<<<dim3(3 * C_DIM / 32, KDIM / 32), 256>>>(
        Wqkv, bhi, blo, 3 * C_DIM);
    mma_gemm_kernel<<<dim3(3 * C_DIM / GBN, T_SEQ / GBM), 256, G_SMEM>>>(
        ahi, alo, bhi, blo, bqkv, qkv_p, 3 * C_DIM);

    // ---- RoPE + bf16 split + V transpose ----
    rope_qkv_kernel<<<dim3(T_SEQ / 64, NH), 256>>>();

    // ---- flash attention (epilogue writes GEMM2's A operand) ----
    flash_mma_kernel<<<dim3(T_SEQ / 128, NH), 256, FB_SMEM>>>();

    // ---- GEMM2: out = y @ Wproj + bproj ----
    transpose_split_kernel<<<dim3(C_DIM / 32, KDIM / 32), 256>>>(
        Wproj, bhi, blo, C_DIM);
    mma_gemm_kernel<<<dim3(C_DIM / GBN, T_SEQ / GBM), 256, G_SMEM>>>(
        ahi, alo, bhi, blo, bproj, out, C_DIM);
}

// round 15
// speedup vs baseline: 1.6637x; 1.0714x over previous
#include <cuda_runtime.h>
#include <cuda_bf16.h>
#include <math.h>
#include <stdint.h>

#define T_SEQ 4096
#define C_DIM 1024
#define NH    16
#define HD    64
#define KDIM  1024

// ---------------- scratch (static device arrays, allowed) ---------------------
__device__ float g_qkv[(size_t)T_SEQ * 3 * C_DIM];
__device__ float g_invf[32];
__device__ float g_cos[(size_t)T_SEQ * 32];
__device__ float g_sin[(size_t)T_SEQ * 32];
// GEMM operands (bf16 split, row-major [rows][K])
__device__ __nv_bfloat16 g_Ahi[(size_t)T_SEQ * KDIM];
__device__ __nv_bfloat16 g_Alo[(size_t)T_SEQ * KDIM];
__device__ __nv_bfloat16 g_Bhi[(size_t)3 * C_DIM * KDIM];
__device__ __nv_bfloat16 g_Blo[(size_t)3 * C_DIM * KDIM];
// attention operands (bf16 split)
__device__ __nv_bfloat16 g_Qhi[(size_t)NH * T_SEQ * HD];   // [h][t][d]
__device__ __nv_bfloat16 g_Qlo[(size_t)NH * T_SEQ * HD];
__device__ __nv_bfloat16 g_Khi[(size_t)NH * T_SEQ * HD];
__device__ __nv_bfloat16 g_Klo[(size_t)NH * T_SEQ * HD];
__device__ __nv_bfloat16 g_Vthi[(size_t)NH * HD * T_SEQ];  // [h][d][t]
__device__ __nv_bfloat16 g_Vtlo[(size_t)NH * HD * T_SEQ];

// ---------------- helpers ------------------------------------------------------
__device__ __forceinline__ uint32_t smem_u32(const void* p) {
    uint32_t a;
    asm("{ .reg .u64 t; cvta.to.shared.u64 t, %1; cvt.u32.u64 %0, t; }"
        : "=r"(a) : "l"(p));
    return a;
}
__device__ __forceinline__ void cp16(uint32_t dst, const void* src) {
    asm volatile("cp.async.cg.shared.global [%0], [%1], 16;"
                 :: "r"(dst), "l"(src));
}
#define CP_COMMIT()  asm volatile("cp.async.commit_group;" ::: "memory")
#define CP_WAIT1()   asm volatile("cp.async.wait_group 1;" ::: "memory")
#define CP_WAITALL() asm volatile("cp.async.wait_all;" ::: "memory")

#define LDSM4(r, addr)                                                          \
    asm volatile("ldmatrix.sync.aligned.m8n8.x4.shared.b16 {%0,%1,%2,%3}, [%4];"\
                 : "=r"((r)[0]), "=r"((r)[1]), "=r"((r)[2]), "=r"((r)[3])       \
                 : "r"(addr))

#define MMA16816(c, a, b0, b1)                                                  \
    asm volatile("mma.sync.aligned.m16n8k16.row.col.f32.bf16.bf16.f32 "         \
                 "{%0,%1,%2,%3}, {%4,%5,%6,%7}, {%8,%9}, {%0,%1,%2,%3};"        \
                 : "+f"((c)[0]), "+f"((c)[1]), "+f"((c)[2]), "+f"((c)[3])       \
                 : "r"((a)[0]), "r"((a)[1]), "r"((a)[2]), "r"((a)[3]),          \
                   "r"(b0), "r"(b1))

// swizzle for [rows][64B] tiles (GEMM path)
__device__ __forceinline__ uint32_t swz(uint32_t row, uint32_t kb) {
    return row * 64u + (kb ^ (((row >> 1) & 3u) << 4));
}
// swizzle for [rows][128B] tiles (flash path), c = 16B-chunk index 0..7
__device__ __forceinline__ uint32_t swz128(uint32_t row, uint32_t c) {
    return row * 128u + ((c ^ (row & 7u)) << 4);
}
__device__ __forceinline__ uint32_t packbf(__nv_bfloat16 a, __nv_bfloat16 b) {
    __nv_bfloat162 t;
    t.x = a; t.y = b;
    return *reinterpret_cast<uint32_t*>(&t);
}
// pack truncated-bf16 of (a -> low half, b -> high half) in one PRMT
__device__ __forceinline__ uint32_t prmt_hi(float a, float b) {
    uint32_t r;
    asm("prmt.b32 %0, %1, %2, 0x7632;"
        : "=r"(r) : "r"(__float_as_uint(a)), "r"(__float_as_uint(b)));
    return r;
}
// packed rn cvt: x -> low bf16, y -> high bf16
__device__ __forceinline__ uint32_t cvtbf2(float x, float y) {
    uint32_t r;
    asm("cvt.rn.bf16x2.f32 %0, %1, %2;" : "=r"(r) : "f"(y), "f"(x));
    return r;
}
__device__ __forceinline__ float trunc_res(float p) {
    return p - __uint_as_float(__float_as_uint(p) & 0xFFFF0000u);
}

// ---------------- trig tables (bit-exact with previous per-thread math) --------
__global__ void init_invfreq_kernel() {
    int j = threadIdx.x;
    if (j < 32) {
        double e = (double)(2 * j) / 64.0;
        g_invf[j] = (float)exp(-e * log(10000.0));
    }
}

__device__ __forceinline__ float reduce_2pi(float theta) {
    double k = nearbyint((double)theta * 0.15915494309189535);
    return (float)((double)theta - k * 6.283185307179586);
}

__global__ void init_trig_kernel() {   // grid: T_SEQ*32/256, block: 256
    int idx = blockIdx.x * blockDim.x + threadIdx.x;
    if (idx >= T_SEQ * 32) return;
    int t = idx >> 5, j = idx & 31;
    float th = (float)t * g_invf[j];   // same fp32 rounding as before
    float r = reduce_2pi(th);
    float s, c;
    sincosf(r, &s, &c);
    g_cos[idx] = c;
    g_sin[idx] = s;
}

// ---------------- fp32 -> bf16 hi/lo split (row-major) -------------------------
__global__ void split_kernel(const float* __restrict__ src,
                             __nv_bfloat16* __restrict__ hi,
                             __nv_bfloat16* __restrict__ lo, int total) {
    int idx = blockIdx.x * blockDim.x + threadIdx.x;
    if (idx >= total) return;
    int m = idx >> 7;
    int k0 = (idx & 127) * 8;
    float4 a = *(const float4*)(src + (size_t)m * KDIM + k0);
    float4 b = *(const float4*)(src + (size_t)m * KDIM + k0 + 4);
    float v[8] = {a.x, a.y, a.z, a.w, b.x, b.y, b.z, b.w};
    __nv_bfloat16 h[8], l[8];
#pragma unroll
    for (int j = 0; j < 8; j++) {
        h[j] = __float2bfloat16(v[j]);
        l[j] = __float2bfloat16(v[j] - __bfloat162float(h[j]));
    }
    *(uint4*)(hi + (size_t)m * KDIM + k0) = *(uint4*)h;
    *(uint4*)(lo + (size_t)m * KDIM + k0) = *(uint4*)l;
}

// ---------------- W [K,N] -> Bt [N,K] bf16 hi/lo -------------------------------
__global__ void transpose_split_kernel(const float* __restrict__ W,
                                       __nv_bfloat16* __restrict__ hi,
                                       __nv_bfloat16* __restrict__ lo, int N) {
    __shared__ float s[32][33];
    int n0 = blockIdx.x * 32, k0 = blockIdx.y * 32;
    int t = threadIdx.x;
#pragma unroll
    for (int i = 0; i < 4; i++) {
        int e = t + i * 256;
        int kl = e >> 5, nl = e & 31;
        s[kl][nl] = W[(size_t)(k0 + kl) * N + n0 + nl];
    }
    __syncthreads();
    if (t < 128) {
        int nl = t >> 2, kg = t & 3, kl0 = kg * 8;
        int n = n0 + nl, k = k0 + kl0;
        __nv_bfloat16 h[8], l[8];
#pragma unroll
        for (int j = 0; j < 8; j++) {
            float v = s[kl0 + j][nl];
            h[j] = __float2bfloat16(v);
            l[j] = __float2bfloat16(v - __bfloat162float(h[j]));
        }
        *(uint4*)(hi + (size_t)n * KDIM + k) = *(uint4*)h;
        *(uint4*)(lo + (size_t)n * KDIM + k) = *(uint4*)l;
    }
}

// ---------------- mma.sync dense GEMM (R7 validated: 128x64, BK=32) ------------
#define GBM 128
#define GBN 64
#define GBK 32
#define G_STAGES 3
#define G_STAGE_BYTES 24576   // Ahi 8K | Alo 8K | Bhi 4K | Blo 4K
#define G_SMEM (G_STAGES * G_STAGE_BYTES + 1024)

__global__ __launch_bounds__(256, 2)
void mma_gemm_kernel(const __nv_bfloat16* __restrict__ Ahi,
                     const __nv_bfloat16* __restrict__ Alo,
                     const __nv_bfloat16* __restrict__ Bhi,
                     const __nv_bfloat16* __restrict__ Blo,
                     const float* __restrict__ bias,
                     float* __restrict__ C, int N)
{
    extern __shared__ char sraw[];
    char* smp = (char*)(((uintptr_t)sraw + 1023) & ~(uintptr_t)1023);
    uint32_t sb = smem_u32(smp);

    int tid = threadIdx.x, lane = tid & 31, w = tid >> 5;
    int m0 = blockIdx.y * GBM, n0 = blockIdx.x * GBN;
    int mw = (w >> 1) * 32, nw = (w & 1) * 32;

    const char* gA[2] = {(const char*)(Ahi + (size_t)m0 * KDIM),
                         (const char*)(Alo + (size_t)m0 * KDIM)};
    const char* gB[2] = {(const char*)(Bhi + (size_t)n0 * KDIM),
                         (const char*)(Blo + (size_t)n0 * KDIM)};

    int arow0 = tid >> 2,         akch0 = tid & 3;
    int arow1 = (tid + 256) >> 2, akch1 = tid & 3;
    int brow  = tid >> 2,         bkch  = tid & 3;

    auto load_stage = [&](int kc, int s) {
        uint32_t base = sb + (uint32_t)s * G_STAGE_BYTES;
        size_t gk = (size_t)kc * 64;
#pragma unroll
        for (int h = 0; h < 2; h++) {
            cp16(base + h * 8192 + swz(arow0, akch0 * 16),
                 gA[h] + (size_t)arow0 * (KDIM * 2) + gk + akch0 * 16);
            cp16(base + h * 8192 + swz(arow1, akch1 * 16),
                 gA[h] + (size_t)arow1 * (KDIM * 2) + gk + akch1 * 16);
            cp16(base + 16384 + h * 4096 + swz(brow, bkch * 16),
                 gB[h] + (size_t)brow * (KDIM * 2) + gk + bkch * 16);
        }
        CP_COMMIT();
    };

    float acc[2][4][4];
#pragma unroll
    for (int i = 0; i < 2; i++)
#pragma unroll
        for (int j = 0; j < 4; j++)
#pragma unroll
            for (int k = 0; k < 4; k++) acc[i][j][k] = 0.f;

    const int KITERS = KDIM / GBK;
    load_stage(0, 0);
    load_stage(1, 1);

    for (int kc = 0; kc < KITERS; kc++) {
        CP_WAIT1();
        __syncthreads();
        if (kc + 2 < KITERS) load_stage(kc + 2, (kc + 2) % G_STAGES);
        else CP_COMMIT();

        uint32_t sbase = sb + (uint32_t)(kc % G_STAGES) * G_STAGE_BYTES;
#pragma unroll
        for (int ks = 0; ks < 2; ks++) {
            uint32_t ah[2][4], al[2][4], bh[2][4], bl[2][4];
            int kbA = ks * 32 + ((lane >> 4) << 4);
#pragma unroll
            for (int mt = 0; mt < 2; mt++) {
                int row = mw + mt * 16 + (lane & 7) + (((lane >> 3) & 1) << 3);
                uint32_t a = sbase + swz(row, kbA);
                LDSM4(ah[mt], a);
                LDSM4(al[mt], a + 8192);
            }
            int kbB = ks * 32 + (((lane >> 3) & 1) << 4);
#pragma unroll
            for (int p = 0; p < 2; p++) {
                int row = nw + p * 16 + (lane & 7) + (((lane >> 4) & 1) << 3);
                uint32_t a = sbase + 16384 + swz(row, kbB);
                LDSM4(bh[p], a);
                LDSM4(bl[p], a + 4096);
            }
#pragma unroll
            for (int mt = 0; mt < 2; mt++)
#pragma unroll
                for (int nt = 0; nt < 4; nt++) {
                    int p = nt >> 1, q = (nt & 1) * 2;
                    MMA16816(acc[mt][nt], ah[mt], bh[p][q], bh[p][q + 1]);
                    MMA16816(acc[mt][nt], ah[mt], bl[p][q], bl[p][q + 1]);
                    MMA16816(acc[mt][nt], al[mt], bh[p][q], bh[p][q + 1]);
                }
        }
    }
    CP_WAITALL();

#pragma unroll
    for (int mt = 0; mt < 2; mt++)
#pragma unroll
        for (int nt = 0; nt < 4; nt++) {
            int row = m0 + mw + mt * 16 + (lane >> 2);
            int col = n0 + nw + nt * 8 + 2 * (lane & 3);
            float b0 = bias[col], b1 = bias[col + 1];
            float2 v0 = make_float2(acc[mt][nt][0] + b0, acc[mt][nt][1] + b1);
            float2 v1 = make_float2(acc[mt][nt][2] + b0, acc[mt][nt][3] + b1);
            *(float2*)(C + (size_t)row * N + col)       = v0;
            *(float2*)(C + (size_t)(row + 8) * N + col) = v1;
        }
}

// ---------------- RoPE (table-driven) + bf16 split + V-transpose ---------------
__global__ __launch_bounds__(256)
void rope_qkv_kernel() {
    __shared__ float sV[64][65];
    int h = blockIdx.y, t0 = blockIdx.x * 64, tid = threadIdx.x;

    for (int e = tid; e < 2048; e += 256) {
        int tl = e >> 5, i = e & 31;
        int t = t0 + tl, d0 = 2 * i, d1 = d0 + 1;
        int j0 = d0 & 31;          // == (d0 < 32 ? d0 : d0-32)

        const float* ct = g_cos + (size_t)t * 32;
        const float* st = g_sin + (size_t)t * 32;
        float c0 = ct[j0], c1 = ct[j0 + 1];
        float s0 = st[j0], s1 = st[j0 + 1];

        const float* src = g_qkv + (size_t)t * (3 * C_DIM) + h * HD;
        float q0 = src[d0],             q1 = src[d1];
        float k0 = src[C_DIM + d0],     k1 = src[C_DIM + d1];
        float v0 = src[2 * C_DIM + d0], v1 = src[2 * C_DIM + d1];

        float qa = q0 * c0 - q1 * s0, qb = q1 * c1 + q0 * s1;
        float ka = k0 * c0 - k1 * s0, kb = k1 * c1 + k0 * s1;

        __nv_bfloat16 qah = __float2bfloat16(qa);
        __nv_bfloat16 qbh = __float2bfloat16(qb);
        __nv_bfloat16 kah = __float2bfloat16(ka);
        __nv_bfloat16 kbh = __float2bfloat16(kb);
        __nv_bfloat16 qal = __float2bfloat16(qa - __bfloat162float(qah));
        __nv_bfloat16 qbl = __float2bfloat16(qb - __bfloat162float(qbh));
        __nv_bfloat16 kal = __float2bfloat16(ka - __bfloat162float(kah));
        __nv_bfloat16 kbl = __float2bfloat16(kb - __bfloat162float(kbh));

        size_t dst = ((size_t)h * T_SEQ + t) * HD + d0;
        *(uint32_t*)(g_Qhi + dst) = packbf(qah, qbh);
        *(uint32_t*)(g_Qlo + dst) = packbf(qal, qbl);
        *(uint32_t*)(g_Khi + dst) = packbf(kah, kbh);
        *(uint32_t*)(g_Klo + dst) = packbf(kal, kbl);

        sV[tl][d0] = v0;
        sV[tl][d1] = v1;
    }
    __syncthreads();
    for (int e = tid; e < 2048; e += 256) {
        int d = e >> 5, tp = (e & 31) * 2;
        float v0 = sV[tp][d], v1 = sV[tp + 1][d];
        __nv_bfloat16 h0 = __float2bfloat16(v0);
        __nv_bfloat16 h1 = __float2bfloat16(v1);
        __nv_bfloat16 l0 = __float2bfloat16(v0 - __bfloat162float(h0));
        __nv_bfloat16 l1 = __float2bfloat16(v1 - __bfloat162float(h1));
        size_t dst = ((size_t)h * HD + d) * T_SEQ + t0 + tp;
        *(uint32_t*)(g_Vthi + dst) = packbf(h0, h1);
        *(uint32_t*)(g_Vtlo + dst) = packbf(l0, l1);
    }
}

// ---------------- Flash attention, mma.sync bf16-split (R10 structure) ---------
// Br=128 (8 warps x 16 rows), Bc=64, 2-stage cp.async K/Vt tiles.
// Epilogue writes hi/lo bf16 split of O directly into g_Ahi/g_Alo for GEMM2.
#define FB_STAGE 32768     // Khi 8K | Klo 8K | Vthi 8K | Vtlo 8K
#define FB_SMEM  (2 * FB_STAGE + 1024)

__global__ __launch_bounds__(256, 2)
void flash_mma_kernel() {
    extern __shared__ char sraw[];
    char* smp = (char*)(((uintptr_t)sraw + 127) & ~(uintptr_t)127);
    uint32_t sb = smem_u32(smp);

    int tid = threadIdx.x, lane = tid & 31, w = tid >> 5;
    int h  = blockIdx.y;
    int qt = (int)gridDim.x - 1 - (int)blockIdx.x;
    int wrow = w * 16;
    int qr = lane >> 2, qc2 = 2 * (lane & 3);

    // ---- preload Q fragments (hi/lo) from global ----
    uint32_t aQh[4][4], aQl[4][4];
    {
        const __nv_bfloat16* Qh =
            g_Qhi + ((size_t)h * T_SEQ + qt * 128 + wrow + qr) * HD;
        const __nv_bfloat16* Ql =
            g_Qlo + ((size_t)h * T_SEQ + qt * 128 + wrow + qr) * HD;
#pragma unroll
        for (int ks = 0; ks < 4; ks++) {
            int k0 = ks * 16 + qc2;
            aQh[ks][0] = *(const uint32_t*)(Qh + k0);
            aQh[ks][1] = *(const uint32_t*)(Qh + 8 * HD + k0);
            aQh[ks][2] = *(const uint32_t*)(Qh + k0 + 8);
            aQh[ks][3] = *(const uint32_t*)(Qh + 8 * HD + k0 + 8);
            aQl[ks][0] = *(const uint32_t*)(Ql + k0);
            aQl[ks][1] = *(const uint32_t*)(Ql + 8 * HD + k0);
            aQl[ks][2] = *(const uint32_t*)(Ql + k0 + 8);
            aQl[ks][3] = *(const uint32_t*)(Ql + 8 * HD + k0 + 8);
        }
    }

    float o[8][4];
#pragma unroll
    for (int i = 0; i < 8; i++)
#pragma unroll
        for (int j = 0; j < 4; j++) o[i][j] = 0.f;
    float m0 = -1e30f, m1 = -1e30f, l0 = 0.f, l1 = 0.f;

    int ntiles = 2 * qt + 2;

    int lrow = tid >> 2;       // 0..63
    int lc   = tid & 3;        // chunk 0..3 (+4)
    auto load_stage = [&](int j, int buf) {
        uint32_t base = sb + (uint32_t)buf * FB_STAGE;
        const char* kh = (const char*)g_Khi
            + ((size_t)h * T_SEQ + (size_t)j * 64 + lrow) * (HD * 2);
        const char* kl = (const char*)g_Klo
            + ((size_t)h * T_SEQ + (size_t)j * 64 + lrow) * (HD * 2);
        const char* vh = (const char*)g_Vthi
            + (((size_t)h * HD + lrow) * T_SEQ + (size_t)j * 64) * 2;
        const char* vl = (const char*)g_Vtlo
            + (((size_t)h * HD + lrow) * T_SEQ + (size_t)j * 64) * 2;
#pragma unroll
        for (int cc = lc; cc < 8; cc += 4) {
            uint32_t sw = swz128(lrow, cc);
            cp16(base + sw,         kh + cc * 16);
            cp16(base + 8192  + sw, kl + cc * 16);
            cp16(base + 16384 + sw, vh + cc * 16);
            cp16(base + 24576 + sw, vl + cc * 16);
        }
    };

    load_stage(0, 0);
    CP_COMMIT();

    for (int j = 0; j < ntiles; j++) {
        if (j + 1 < ntiles) load_stage(j + 1, (j + 1) & 1);
        CP_COMMIT();
        CP_WAIT1();
        __syncthreads();

        uint32_t st  = sb + (uint32_t)(j & 1) * FB_STAGE;
        uint32_t sKh = st, sVh = st + 16384;

        // ---- S = Q @ K^T (3-term split) ----
        float s[8][4];
#pragma unroll
        for (int i = 0; i < 8; i++)
#pragma unroll
            for (int jj = 0; jj < 4; jj++) s[i][jj] = 0.f;

#pragma unroll
        for (int ks = 0; ks < 4; ks++) {
            int rsel = (lane & 7) + (((lane >> 4) & 1) << 3);
            int c    = 2 * ks + ((lane >> 3) & 1);
#pragma unroll
            for (int p = 0; p < 4; p++) {
                uint32_t bh[4], bl[4];
                int row = p * 16 + rsel;
                uint32_t a = sKh + swz128(row, c);
                LDSM4(bh, a);
                LDSM4(bl, a + 8192);
#pragma unroll
                for (int sub = 0; sub < 2; sub++) {
                    int nt = p * 2 + sub, q = sub * 2;
                    MMA16816(s[nt], aQh[ks], bh[q], bh[q + 1]);
                    MMA16816(s[nt], aQh[ks], bl[q], bl[q + 1]);
                    MMA16816(s[nt], aQl[ks], bh[q], bh[q + 1]);
                }
            }
        }

        // ---- scale + causal mask (block-uniform branch) ----
        if (j >= 2 * qt) {
            int row0 = qt * 128 + wrow + qr;
#pragma unroll
            for (int nt = 0; nt < 8; nt++) {
                int cb = j * 64 + nt * 8 + qc2;
#pragma unroll
                for (int e = 0; e < 4; e++) {
                    float v = s[nt][e] * 0.125f;
                    int col = cb + (e & 1);
                    int row = row0 + (e >> 1) * 8;
                    if (col > row) v = -1e30f;
                    s[nt][e] = v;
                }
            }
        } else {
#pragma unroll
            for (int nt = 0; nt < 8; nt++)
#pragma unroll
                for (int e = 0; e < 4; e++)
                    s[nt][e] *= 0.125f;
        }

        // ---- online softmax on fragments ----
        float mx0 = -1e30f, mx1 = -1e30f;
#pragma unroll
        for (int nt = 0; nt < 8; nt++) {
            mx0 = fmaxf(mx0, fmaxf(s[nt][0], s[nt][1]));
            mx1 = fmaxf(mx1, fmaxf(s[nt][2], s[nt][3]));
        }
        mx0 = fmaxf(mx0, __shfl_xor_sync(0xffffffffu, mx0, 1));
        mx0 = fmaxf(mx0, __shfl_xor_sync(0xffffffffu, mx0, 2));
        mx1 = fmaxf(mx1, __shfl_xor_sync(0xffffffffu, mx1, 1));
        mx1 = fmaxf(mx1, __shfl_xor_sync(0xffffffffu, mx1, 2));

        float mn0 = fmaxf(m0, mx0), mn1 = fmaxf(m1, mx1);
        float a0 = __expf(m0 - mn0), a1 = __expf(m1 - mn1);
        float sum0 = 0.f, sum1 = 0.f;
#pragma unroll
        for (int nt = 0; nt < 8; nt++) {
            float p0 = __expf(s[nt][0] - mn0);
            float p1 = __expf(s[nt][1] - mn0);
            float p2 = __expf(s[nt][2] - mn1);
            float p3 = __expf(s[nt][3] - mn1);
            s[nt][0] = p0; s[nt][1] = p1; s[nt][2] = p2; s[nt][3] = p3;
            sum0 += p0 + p1;
            sum1 += p2 + p3;
        }
        sum0 += __shfl_xor_sync(0xffffffffu, sum0, 1);
        sum0 += __shfl_xor_sync(0xffffffffu, sum0, 2);
        sum1 += __shfl_xor_sync(0xffffffffu, sum1, 1);
        sum1 += __shfl_xor_sync(0xffffffffu, sum1, 2);
        l0 = l0 * a0 + sum0;
        l1 = l1 * a1 + sum1;
        m0 = mn0; m1 = mn1;

        // ---- O rescale, skipped when all alphas are exactly 1 ----
        if (!__all_sync(0xffffffffu, (a0 == 1.f) && (a1 == 1.f))) {
#pragma unroll
            for (int i = 0; i < 8; i++) {
                o[i][0] *= a0; o[i][1] *= a0;
                o[i][2] *= a1; o[i][3] *= a1;
            }
        }

        // ---- repack P -> A fragments (cheap truncation split) ----
        uint32_t aPh[4][4], aPl[4][4];
#pragma unroll
        for (int ks = 0; ks < 4; ks++) {
#pragma unroll
            for (int half = 0; half < 2; half++) {
                int nt = 2 * ks + half;
                aPh[ks][half * 2]     = prmt_hi(s[nt][0], s[nt][1]);
                aPh[ks][half * 2 + 1] = prmt_hi(s[nt][2], s[nt][3]);
                aPl[ks][half * 2]     = cvtbf2(trunc_res(s[nt][0]),
                                               trunc_res(s[nt][1]));
                aPl[ks][half * 2 + 1] = cvtbf2(trunc_res(s[nt][2]),
                                               trunc_res(s[nt][3]));
            }
        }

        // ---- O += P @ V (3-term split) ----
#pragma unroll
        for (int ks = 0; ks < 4; ks++) {
            int rsel = (lane & 7) + (((lane >> 4) & 1) << 3);
            int c    = 2 * ks + ((lane >> 3) & 1);
#pragma unroll
            for (int p = 0; p < 4; p++) {
                uint32_t bh[4], bl[4];
                int row = p * 16 + rsel;
                uint32_t a = sVh + swz128(row, c);
                LDSM4(bh, a);
                LDSM4(bl, a + 8192);
#pragma unroll
                for (int sub = 0; sub < 2; sub++) {
                    int nt = p * 2 + sub, q = sub * 2;
                    MMA16816(o[nt], aPh[ks], bh[q], bh[q + 1]);
                    MMA16816(o[nt], aPh[ks], bl[q], bl[q + 1]);
                    MMA16816(o[nt], aPl[ks], bh[q], bh[q + 1]);
                }
            }
        }
        __syncthreads();
    }

    // ---- epilogue: O/l, split to bf16 hi/lo for GEMM2 ----
    float li0 = 1.f / l0, li1 = 1.f / l1;
    int r0 = qt * 128 + wrow + qr;
#pragma unroll
    for (int nt = 0; nt < 8; nt++) {
        int gcol = h * HD + nt * 8 + qc2;
        float f0 = o[nt][0] * li0, f1 = o[nt][1] * li0;
        float f2 = o[nt][2] * li1, f3 = o[nt][3] * li1;
        __nv_bfloat16 h0 = __float2bfloat16(f0);
        __nv_bfloat16 h1 = __float2bfloat16(f1);
        __nv_bfloat16 h2 = __float2bfloat16(f2);
        __nv_bfloat16 h3 = __float2bfloat16(f3);
        size_t o0 = (size_t)r0 * KDIM + gcol;
        size_t o1 = (size_t)(r0 + 8) * KDIM + gcol;
        *(uint32_t*)(g_Ahi + o0) = packbf(h0, h1);
        *(uint32_t*)(g_Alo + o0) = packbf(
            __float2bfloat16(f0 - __bfloat162float(h0)),
            __float2bfloat16(f1 - __bfloat162float(h1)));
        *(uint32_t*)(g_Ahi + o1) = packbf(h2, h3);
        *(uint32_t*)(g_Alo + o1) = packbf(
            __float2bfloat16(f2 - __bfloat162float(h2)),
            __float2bfloat16(f3 - __bfloat162float(h3)));
    }
}

// ---------------- launch ------------------------------------------------------
extern "C" void kernel_launch(void* const* d_in, const int* in_sizes, int n_in,
                              void* d_out, int out_size)
{
    const float* x     = (const float*)d_in[0];
    const float* Wqkv  = (const float*)d_in[1];
    const float* bqkv  = (const float*)d_in[2];
    const float* Wproj = (const float*)d_in[3];
    const float* bproj = (const float*)d_in[4];
    float* out = (float*)d_out;

    float* qkv_p;
    __nv_bfloat16 *ahi, *alo, *bhi, *blo;
    cudaGetSymbolAddress((void**)&qkv_p, g_qkv);
    cudaGetSymbolAddress((void**)&ahi, g_Ahi);
    cudaGetSymbolAddress((void**)&alo, g_Alo);
    cudaGetSymbolAddress((void**)&bhi, g_Bhi);
    cudaGetSymbolAddress((void**)&blo, g_Blo);

    cudaFuncSetAttribute(mma_gemm_kernel,
                         cudaFuncAttributeMaxDynamicSharedMemorySize, G_SMEM);
    cudaFuncSetAttribute(flash_mma_kernel,
                         cudaFuncAttributeMaxDynamicSharedMemorySize, FB_SMEM);

    init_invfreq_kernel<<<1, 32>>>();
    init_trig_kernel<<<(T_SEQ * 32) / 256, 256>>>();

    // ---- GEMM1: qkv = x @ Wqkv + bqkv ----
    split_kernel<<<(T_SEQ * (KDIM / 8)) / 256, 256>>>(x, ahi, alo,
                                                      T_SEQ * (KDIM / 8));
    transpose_split_kernel<<<dim3(3 * C_DIM / 32, KDIM / 32), 256>>>(
        Wqkv, bhi, blo, 3 * C_DIM);
    mma_gemm_kernel<<<dim3(3 * C_DIM / GBN, T_SEQ / GBM), 256, G_SMEM>>>(
        ahi, alo, bhi, blo, bqkv, qkv_p, 3 * C_DIM);

    // ---- RoPE (table) + bf16 split + V transpose ----
    rope_qkv_kernel<<<dim3(T_SEQ / 64, NH), 256>>>();

    // ---- flash attention (epilogue writes GEMM2's A operand) ----
    flash_mma_kernel<<<dim3(T_SEQ / 128, NH), 256, FB_SMEM>>>();

    // ---- GEMM2: out = y @ Wproj + bproj ----
    transpose_split_kernel<<<dim3(C_DIM / 32, KDIM / 32), 256>>>(
        Wproj, bhi, blo, C_DIM);
    mma_gemm_kernel<<<dim3(C_DIM / GBN, T_SEQ / GBM), 256, G_SMEM>>>(
        ahi, alo, bhi, blo, bproj, out, C_DIM);
}

// round 16
// speedup vs baseline: 1.6840x; 1.0122x over previous
#include <cuda_runtime.h>
#include <cuda_bf16.h>
#include <math.h>
#include <stdint.h>

#define T_SEQ 4096
#define C_DIM 1024
#define NH    16
#define HD    64
#define KDIM  1024

// ---------------- scratch (static device arrays, allowed) ---------------------
__device__ float g_Vf[(size_t)T_SEQ * C_DIM];   // fp32 V staging [t][h*64+d]
__device__ float g_invf[32];
__device__ float g_cos[(size_t)T_SEQ * 32];
__device__ float g_sin[(size_t)T_SEQ * 32];
// GEMM operands (bf16 split, row-major [rows][K])
__device__ __nv_bfloat16 g_Ahi[(size_t)T_SEQ * KDIM];
__device__ __nv_bfloat16 g_Alo[(size_t)T_SEQ * KDIM];
__device__ __nv_bfloat16 g_Bhi[(size_t)3 * C_DIM * KDIM];
__device__ __nv_bfloat16 g_Blo[(size_t)3 * C_DIM * KDIM];
// attention operands (bf16 split)
__device__ __nv_bfloat16 g_Qhi[(size_t)NH * T_SEQ * HD];   // [h][t][d]
__device__ __nv_bfloat16 g_Qlo[(size_t)NH * T_SEQ * HD];
__device__ __nv_bfloat16 g_Khi[(size_t)NH * T_SEQ * HD];
__device__ __nv_bfloat16 g_Klo[(size_t)NH * T_SEQ * HD];
__device__ __nv_bfloat16 g_Vthi[(size_t)NH * HD * T_SEQ];  // [h][d][t]
__device__ __nv_bfloat16 g_Vtlo[(size_t)NH * HD * T_SEQ];

// ---------------- helpers ------------------------------------------------------
__device__ __forceinline__ uint32_t smem_u32(const void* p) {
    uint32_t a;
    asm("{ .reg .u64 t; cvta.to.shared.u64 t, %1; cvt.u32.u64 %0, t; }"
        : "=r"(a) : "l"(p));
    return a;
}
__device__ __forceinline__ void cp16(uint32_t dst, const void* src) {
    asm volatile("cp.async.cg.shared.global [%0], [%1], 16;"
                 :: "r"(dst), "l"(src));
}
#define CP_COMMIT()  asm volatile("cp.async.commit_group;" ::: "memory")
#define CP_WAIT1()   asm volatile("cp.async.wait_group 1;" ::: "memory")
#define CP_WAITALL() asm volatile("cp.async.wait_all;" ::: "memory")

#define LDSM4(r, addr)                                                          \
    asm volatile("ldmatrix.sync.aligned.m8n8.x4.shared.b16 {%0,%1,%2,%3}, [%4];"\
                 : "=r"((r)[0]), "=r"((r)[1]), "=r"((r)[2]), "=r"((r)[3])       \
                 : "r"(addr))

#define MMA16816(c, a, b0, b1)                                                  \
    asm volatile("mma.sync.aligned.m16n8k16.row.col.f32.bf16.bf16.f32 "         \
                 "{%0,%1,%2,%3}, {%4,%5,%6,%7}, {%8,%9}, {%0,%1,%2,%3};"        \
                 : "+f"((c)[0]), "+f"((c)[1]), "+f"((c)[2]), "+f"((c)[3])       \
                 : "r"((a)[0]), "r"((a)[1]), "r"((a)[2]), "r"((a)[3]),          \
                   "r"(b0), "r"(b1))

// swizzle for [rows][64B] tiles (GEMM path)
__device__ __forceinline__ uint32_t swz(uint32_t row, uint32_t kb) {
    return row * 64u + (kb ^ (((row >> 1) & 3u) << 4));
}
// swizzle for [rows][128B] tiles (flash path), c = 16B-chunk index 0..7
__device__ __forceinline__ uint32_t swz128(uint32_t row, uint32_t c) {
    return row * 128u + ((c ^ (row & 7u)) << 4);
}
__device__ __forceinline__ uint32_t packbf(__nv_bfloat16 a, __nv_bfloat16 b) {
    __nv_bfloat162 t;
    t.x = a; t.y = b;
    return *reinterpret_cast<uint32_t*>(&t);
}
// pack truncated-bf16 of (a -> low half, b -> high half) in one PRMT
__device__ __forceinline__ uint32_t prmt_hi(float a, float b) {
    uint32_t r;
    asm("prmt.b32 %0, %1, %2, 0x7632;"
        : "=r"(r) : "r"(__float_as_uint(a)), "r"(__float_as_uint(b)));
    return r;
}
// packed rn cvt: x -> low bf16, y -> high bf16
__device__ __forceinline__ uint32_t cvtbf2(float x, float y) {
    uint32_t r;
    asm("cvt.rn.bf16x2.f32 %0, %1, %2;" : "=r"(r) : "f"(y), "f"(x));
    return r;
}
__device__ __forceinline__ float trunc_res(float p) {
    return p - __uint_as_float(__float_as_uint(p) & 0xFFFF0000u);
}
// rn hi/lo split of a pair -> two packed words
__device__ __forceinline__ void split_pair(float a, float b,
                                           uint32_t& hi, uint32_t& lo) {
    __nv_bfloat16 ah = __float2bfloat16(a);
    __nv_bfloat16 bh = __float2bfloat16(b);
    hi = packbf(ah, bh);
    lo = packbf(__float2bfloat16(a - __bfloat162float(ah)),
                __float2bfloat16(b - __bfloat162float(bh)));
}

// ---------------- trig tables --------------------------------------------------
__global__ void init_invfreq_kernel() {
    int j = threadIdx.x;
    if (j < 32) {
        double e = (double)(2 * j) / 64.0;
        g_invf[j] = (float)exp(-e * log(10000.0));
    }
}

__device__ __forceinline__ float reduce_2pi(float theta) {
    double k = nearbyint((double)theta * 0.15915494309189535);
    return (float)((double)theta - k * 6.283185307179586);
}

__global__ void init_trig_kernel() {
    int idx = blockIdx.x * blockDim.x + threadIdx.x;
    if (idx >= T_SEQ * 32) return;
    int t = idx >> 5, j = idx & 31;
    float th = (float)t * g_invf[j];
    float r = reduce_2pi(th);
    float s, c;
    sincosf(r, &s, &c);
    g_cos[idx] = c;
    g_sin[idx] = s;
}

// ---------------- fp32 -> bf16 hi/lo split (row-major) -------------------------
__global__ void split_kernel(const float* __restrict__ src,
                             __nv_bfloat16* __restrict__ hi,
                             __nv_bfloat16* __restrict__ lo, int total) {
    int idx = blockIdx.x * blockDim.x + threadIdx.x;
    if (idx >= total) return;
    int m = idx >> 7;
    int k0 = (idx & 127) * 8;
    float4 a = *(const float4*)(src + (size_t)m * KDIM + k0);
    float4 b = *(const float4*)(src + (size_t)m * KDIM + k0 + 4);
    float v[8] = {a.x, a.y, a.z, a.w, b.x, b.y, b.z, b.w};
    __nv_bfloat16 h[8], l[8];
#pragma unroll
    for (int j = 0; j < 8; j++) {
        h[j] = __float2bfloat16(v[j]);
        l[j] = __float2bfloat16(v[j] - __bfloat162float(h[j]));
    }
    *(uint4*)(hi + (size_t)m * KDIM + k0) = *(uint4*)h;
    *(uint4*)(lo + (size_t)m * KDIM + k0) = *(uint4*)l;
}

// ---------------- W [K,N] -> Bt [N,K] bf16 hi/lo -------------------------------
__global__ void transpose_split_kernel(const float* __restrict__ W,
                                       __nv_bfloat16* __restrict__ hi,
                                       __nv_bfloat16* __restrict__ lo, int N) {
    __shared__ float s[32][33];
    int n0 = blockIdx.x * 32, k0 = blockIdx.y * 32;
    int t = threadIdx.x;
#pragma unroll
    for (int i = 0; i < 4; i++) {
        int e = t + i * 256;
        int kl = e >> 5, nl = e & 31;
        s[kl][nl] = W[(size_t)(k0 + kl) * N + n0 + nl];
    }
    __syncthreads();
    if (t < 128) {
        int nl = t >> 2, kg = t & 3, kl0 = kg * 8;
        int n = n0 + nl, k = k0 + kl0;
        __nv_bfloat16 h[8], l[8];
#pragma unroll
        for (int j = 0; j < 8; j++) {
            float v = s[kl0 + j][nl];
            h[j] = __float2bfloat16(v);
            l[j] = __float2bfloat16(v - __bfloat162float(h[j]));
        }
        *(uint4*)(hi + (size_t)n * KDIM + k) = *(uint4*)h;
        *(uint4*)(lo + (size_t)n * KDIM + k) = *(uint4*)l;
    }
}

// ---------------- shared GEMM mainloop (128x64, BK=32, 3-stage) ----------------
#define GBM 128
#define GBN 64
#define GBK 32
#define G_STAGES 3
#define G_STAGE_BYTES 24576   // Ahi 8K | Alo 8K | Bhi 4K | Blo 4K
#define G_SMEM (G_STAGES * G_STAGE_BYTES + 1024)

// mainloop body as a macro-free inline: computes acc[2][4][4] for this block.
__device__ __forceinline__ void gemm_mainloop(
    const __nv_bfloat16* Ahi, const __nv_bfloat16* Alo,
    const __nv_bfloat16* Bhi, const __nv_bfloat16* Blo,
    int m0, int n0, uint32_t sb, int tid, int lane, int mw, int nw,
    float acc[2][4][4])
{
    const char* gA[2] = {(const char*)(Ahi + (size_t)m0 * KDIM),
                         (const char*)(Alo + (size_t)m0 * KDIM)};
    const char* gB[2] = {(const char*)(Bhi + (size_t)n0 * KDIM),
                         (const char*)(Blo + (size_t)n0 * KDIM)};

    int arow0 = tid >> 2,         akch0 = tid & 3;
    int arow1 = (tid + 256) >> 2, akch1 = tid & 3;
    int brow  = tid >> 2,         bkch  = tid & 3;

    auto load_stage = [&](int kc, int s) {
        uint32_t base = sb + (uint32_t)s * G_STAGE_BYTES;
        size_t gk = (size_t)kc * 64;
#pragma unroll
        for (int h = 0; h < 2; h++) {
            cp16(base + h * 8192 + swz(arow0, akch0 * 16),
                 gA[h] + (size_t)arow0 * (KDIM * 2) + gk + akch0 * 16);
            cp16(base + h * 8192 + swz(arow1, akch1 * 16),
                 gA[h] + (size_t)arow1 * (KDIM * 2) + gk + akch1 * 16);
            cp16(base + 16384 + h * 4096 + swz(brow, bkch * 16),
                 gB[h] + (size_t)brow * (KDIM * 2) + gk + bkch * 16);
        }
        CP_COMMIT();
    };

    const int KITERS = KDIM / GBK;
    load_stage(0, 0);
    load_stage(1, 1);

    for (int kc = 0; kc < KITERS; kc++) {
        CP_WAIT1();
        __syncthreads();
        if (kc + 2 < KITERS) load_stage(kc + 2, (kc + 2) % G_STAGES);
        else CP_COMMIT();

        uint32_t sbase = sb + (uint32_t)(kc % G_STAGES) * G_STAGE_BYTES;
#pragma unroll
        for (int ks = 0; ks < 2; ks++) {
            uint32_t ah[2][4], al[2][4], bh[2][4], bl[2][4];
            int kbA = ks * 32 + ((lane >> 4) << 4);
#pragma unroll
            for (int mt = 0; mt < 2; mt++) {
                int row = mw + mt * 16 + (lane & 7) + (((lane >> 3) & 1) << 3);
                uint32_t a = sbase + swz(row, kbA);
                LDSM4(ah[mt], a);
                LDSM4(al[mt], a + 8192);
            }
            int kbB = ks * 32 + (((lane >> 3) & 1) << 4);
#pragma unroll
            for (int p = 0; p < 2; p++) {
                int row = nw + p * 16 + (lane & 7) + (((lane >> 4) & 1) << 3);
                uint32_t a = sbase + 16384 + swz(row, kbB);
                LDSM4(bh[p], a);
                LDSM4(bl[p], a + 4096);
            }
#pragma unroll
            for (int mt = 0; mt < 2; mt++)
#pragma unroll
                for (int nt = 0; nt < 4; nt++) {
                    int p = nt >> 1, q = (nt & 1) * 2;
                    MMA16816(acc[mt][nt], ah[mt], bh[p][q], bh[p][q + 1]);
                    MMA16816(acc[mt][nt], ah[mt], bl[p][q], bl[p][q + 1]);
                    MMA16816(acc[mt][nt], al[mt], bh[p][q], bh[p][q + 1]);
                }
        }
    }
    CP_WAITALL();
}

// ---------------- plain GEMM (used for proj) -----------------------------------
__global__ __launch_bounds__(256, 2)
void mma_gemm_kernel(const __nv_bfloat16* __restrict__ Ahi,
                     const __nv_bfloat16* __restrict__ Alo,
                     const __nv_bfloat16* __restrict__ Bhi,
                     const __nv_bfloat16* __restrict__ Blo,
                     const float* __restrict__ bias,
                     float* __restrict__ C, int N)
{
    extern __shared__ char sraw[];
    char* smp = (char*)(((uintptr_t)sraw + 1023) & ~(uintptr_t)1023);
    uint32_t sb = smem_u32(smp);

    int tid = threadIdx.x, lane = tid & 31, w = tid >> 5;
    int m0 = blockIdx.y * GBM, n0 = blockIdx.x * GBN;
    int mw = (w >> 1) * 32, nw = (w & 1) * 32;

    float acc[2][4][4];
#pragma unroll
    for (int i = 0; i < 2; i++)
#pragma unroll
        for (int j = 0; j < 4; j++)
#pragma unroll
            for (int k = 0; k < 4; k++) acc[i][j][k] = 0.f;

    gemm_mainloop(Ahi, Alo, Bhi, Blo, m0, n0, sb, tid, lane, mw, nw, acc);

#pragma unroll
    for (int mt = 0; mt < 2; mt++)
#pragma unroll
        for (int nt = 0; nt < 4; nt++) {
            int row = m0 + mw + mt * 16 + (lane >> 2);
            int col = n0 + nw + nt * 8 + 2 * (lane & 3);
            float b0 = bias[col], b1 = bias[col + 1];
            float2 v0 = make_float2(acc[mt][nt][0] + b0, acc[mt][nt][1] + b1);
            float2 v1 = make_float2(acc[mt][nt][2] + b0, acc[mt][nt][3] + b1);
            *(float2*)(C + (size_t)row * N + col)       = v0;
            *(float2*)(C + (size_t)(row + 8) * N + col) = v1;
        }
}

// ---------------- QKV GEMM with fused RoPE + bf16-split epilogue ---------------
__global__ __launch_bounds__(256, 2)
void mma_gemm_qkv_kernel(const __nv_bfloat16* __restrict__ Ahi,
                         const __nv_bfloat16* __restrict__ Alo,
                         const __nv_bfloat16* __restrict__ Bhi,
                         const __nv_bfloat16* __restrict__ Blo,
                         const float* __restrict__ bias)
{
    extern __shared__ char sraw[];
    char* smp = (char*)(((uintptr_t)sraw + 1023) & ~(uintptr_t)1023);
    uint32_t sb = smem_u32(smp);

    int tid = threadIdx.x, lane = tid & 31, w = tid >> 5;
    int m0 = blockIdx.y * GBM, n0 = blockIdx.x * GBN;
    int mw = (w >> 1) * 32, nw = (w & 1) * 32;

    float acc[2][4][4];
#pragma unroll
    for (int i = 0; i < 2; i++)
#pragma unroll
        for (int j = 0; j < 4; j++)
#pragma unroll
            for (int k = 0; k < 4; k++) acc[i][j][k] = 0.f;

    gemm_mainloop(Ahi, Alo, Bhi, Blo, m0, n0, sb, tid, lane, mw, nw, acc);

    int region = n0 >> 10;   // 0 = Q, 1 = K, 2 = V (block-uniform)

#pragma unroll
    for (int mt = 0; mt < 2; mt++)
#pragma unroll
        for (int nt = 0; nt < 4; nt++) {
            int t   = m0 + mw + mt * 16 + (lane >> 2);
            int col = n0 + nw + nt * 8 + 2 * (lane & 3);
            float b0 = bias[col], b1 = bias[col + 1];
            float v0 = acc[mt][nt][0] + b0, v1 = acc[mt][nt][1] + b1; // row t
            float v2 = acc[mt][nt][2] + b0, v3 = acc[mt][nt][3] + b1; // row t+8

            if (region == 2) {
                int d = col - 2048;
                *(float2*)(g_Vf + (size_t)t * C_DIM + d)       = make_float2(v0, v1);
                *(float2*)(g_Vf + (size_t)(t + 8) * C_DIM + d) = make_float2(v2, v3);
            } else {
                int g = col & 1023;
                int hh = g >> 6, d0 = g & 63, j0 = d0 & 31;
                // row t
                float c0 = g_cos[(size_t)t * 32 + j0];
                float c1 = g_cos[(size_t)t * 32 + j0 + 1];
                float s0 = g_sin[(size_t)t * 32 + j0];
                float s1 = g_sin[(size_t)t * 32 + j0 + 1];
                float ra = v0 * c0 - v1 * s0, rb = v1 * c1 + v0 * s1;
                // row t+8
                float c0b = g_cos[(size_t)(t + 8) * 32 + j0];
                float c1b = g_cos[(size_t)(t + 8) * 32 + j0 + 1];
                float s0b = g_sin[(size_t)(t + 8) * 32 + j0];
                float s1b = g_sin[(size_t)(t + 8) * 32 + j0 + 1];
                float rc = v2 * c0b - v3 * s0b, rd = v3 * c1b + v2 * s1b;

                uint32_t hi0, lo0, hi1, lo1;
                split_pair(ra, rb, hi0, lo0);
                split_pair(rc, rd, hi1, lo1);

                __nv_bfloat16* dh = (region == 0) ? g_Qhi : g_Khi;
                __nv_bfloat16* dl = (region == 0) ? g_Qlo : g_Klo;
                size_t o0 = ((size_t)hh * T_SEQ + t) * HD + d0;
                size_t o1 = ((size_t)hh * T_SEQ + t + 8) * HD + d0;
                *(uint32_t*)(dh + o0) = hi0;
                *(uint32_t*)(dl + o0) = lo0;
                *(uint32_t*)(dh + o1) = hi1;
                *(uint32_t*)(dl + o1) = lo1;
            }
        }
}

// ---------------- V transpose + bf16 split ([t][c] fp32 -> [h][d][t] bf16) -----
__global__ __launch_bounds__(256)
void v_split_kernel() {
    __shared__ float sV[64][65];
    int h = blockIdx.y, t0 = blockIdx.x * 64, tid = threadIdx.x;

    for (int e = tid; e < 2048; e += 256) {
        int tl = e >> 5, i = e & 31;
        int t = t0 + tl, d0 = 2 * i;
        float2 v = *(const float2*)(g_Vf + (size_t)t * C_DIM + h * HD + d0);
        sV[tl][d0]     = v.x;
        sV[tl][d0 + 1] = v.y;
    }
    __syncthreads();
    for (int e = tid; e < 2048; e += 256) {
        int d = e >> 5, tp = (e & 31) * 2;
        float v0 = sV[tp][d], v1 = sV[tp + 1][d];
        __nv_bfloat16 h0 = __float2bfloat16(v0);
        __nv_bfloat16 h1 = __float2bfloat16(v1);
        __nv_bfloat16 l0 = __float2bfloat16(v0 - __bfloat162float(h0));
        __nv_bfloat16 l1 = __float2bfloat16(v1 - __bfloat162float(h1));
        size_t dst = ((size_t)h * HD + d) * T_SEQ + t0 + tp;
        *(uint32_t*)(g_Vthi + dst) = packbf(h0, h1);
        *(uint32_t*)(g_Vtlo + dst) = packbf(l0, l1);
    }
}

// ---------------- Flash attention, mma.sync bf16-split (R15 validated) ---------
#define FB_STAGE 32768     // Khi 8K | Klo 8K | Vthi 8K | Vtlo 8K
#define FB_SMEM  (2 * FB_STAGE + 1024)

__global__ __launch_bounds__(256, 2)
void flash_mma_kernel() {
    extern __shared__ char sraw[];
    char* smp = (char*)(((uintptr_t)sraw + 127) & ~(uintptr_t)127);
    uint32_t sb = smem_u32(smp);

    int tid = threadIdx.x, lane = tid & 31, w = tid >> 5;
    int h  = blockIdx.y;
    int qt = (int)gridDim.x - 1 - (int)blockIdx.x;
    int wrow = w * 16;
    int qr = lane >> 2, qc2 = 2 * (lane & 3);

    // ---- preload Q fragments (hi/lo) from global ----
    uint32_t aQh[4][4], aQl[4][4];
    {
        const __nv_bfloat16* Qh =
            g_Qhi + ((size_t)h * T_SEQ + qt * 128 + wrow + qr) * HD;
        const __nv_bfloat16* Ql =
            g_Qlo + ((size_t)h * T_SEQ + qt * 128 + wrow + qr) * HD;
#pragma unroll
        for (int ks = 0; ks < 4; ks++) {
            int k0 = ks * 16 + qc2;
            aQh[ks][0] = *(const uint32_t*)(Qh + k0);
            aQh[ks][1] = *(const uint32_t*)(Qh + 8 * HD + k0);
            aQh[ks][2] = *(const uint32_t*)(Qh + k0 + 8);
            aQh[ks][3] = *(const uint32_t*)(Qh + 8 * HD + k0 + 8);
            aQl[ks][0] = *(const uint32_t*)(Ql + k0);
            aQl[ks][1] = *(const uint32_t*)(Ql + 8 * HD + k0);
            aQl[ks][2] = *(const uint32_t*)(Ql + k0 + 8);
            aQl[ks][3] = *(const uint32_t*)(Ql + 8 * HD + k0 + 8);
        }
    }

    float o[8][4];
#pragma unroll
    for (int i = 0; i < 8; i++)
#pragma unroll
        for (int j = 0; j < 4; j++) o[i][j] = 0.f;
    float m0 = -1e30f, m1 = -1e30f, l0 = 0.f, l1 = 0.f;

    int ntiles = 2 * qt + 2;

    int lrow = tid >> 2;       // 0..63
    int lc   = tid & 3;        // chunk 0..3 (+4)
    auto load_stage = [&](int j, int buf) {
        uint32_t base = sb + (uint32_t)buf * FB_STAGE;
        const char* kh = (const char*)g_Khi
            + ((size_t)h * T_SEQ + (size_t)j * 64 + lrow) * (HD * 2);
        const char* kl = (const char*)g_Klo
            + ((size_t)h * T_SEQ + (size_t)j * 64 + lrow) * (HD * 2);
        const char* vh = (const char*)g_Vthi
            + (((size_t)h * HD + lrow) * T_SEQ + (size_t)j * 64) * 2;
        const char* vl = (const char*)g_Vtlo
            + (((size_t)h * HD + lrow) * T_SEQ + (size_t)j * 64) * 2;
#pragma unroll
        for (int cc = lc; cc < 8; cc += 4) {
            uint32_t sw = swz128(lrow, cc);
            cp16(base + sw,         kh + cc * 16);
            cp16(base + 8192  + sw, kl + cc * 16);
            cp16(base + 16384 + sw, vh + cc * 16);
            cp16(base + 24576 + sw, vl + cc * 16);
        }
    };

    load_stage(0, 0);
    CP_COMMIT();

    for (int j = 0; j < ntiles; j++) {
        if (j + 1 < ntiles) load_stage(j + 1, (j + 1) & 1);
        CP_COMMIT();
        CP_WAIT1();
        __syncthreads();

        uint32_t st  = sb + (uint32_t)(j & 1) * FB_STAGE;
        uint32_t sKh = st, sVh = st + 16384;

        // ---- S = Q @ K^T (3-term split) ----
        float s[8][4];
#pragma unroll
        for (int i = 0; i < 8; i++)
#pragma unroll
            for (int jj = 0; jj < 4; jj++) s[i][jj] = 0.f;

#pragma unroll
        for (int ks = 0; ks < 4; ks++) {
            int rsel = (lane & 7) + (((lane >> 4) & 1) << 3);
            int c    = 2 * ks + ((lane >> 3) & 1);
#pragma unroll
            for (int p = 0; p < 4; p++) {
                uint32_t bh[4], bl[4];
                int row = p * 16 + rsel;
                uint32_t a = sKh + swz128(row, c);
                LDSM4(bh, a);
                LDSM4(bl, a + 8192);
#pragma unroll
                for (int sub = 0; sub < 2; sub++) {
                    int nt = p * 2 + sub, q = sub * 2;
                    MMA16816(s[nt], aQh[ks], bh[q], bh[q + 1]);
                    MMA16816(s[nt], aQh[ks], bl[q], bl[q + 1]);
                    MMA16816(s[nt], aQl[ks], bh[q], bh[q + 1]);
                }
            }
        }

        // ---- scale + causal mask (block-uniform branch) ----
        if (j >= 2 * qt) {
            int row0 = qt * 128 + wrow + qr;
#pragma unroll
            for (int nt = 0; nt < 8; nt++) {
                int cb = j * 64 + nt * 8 + qc2;
#pragma unroll
                for (int e = 0; e < 4; e++) {
                    float v = s[nt][e] * 0.125f;
                    int col = cb + (e & 1);
                    int row = row0 + (e >> 1) * 8;
                    if (col > row) v = -1e30f;
                    s[nt][e] = v;
                }
            }
        } else {
#pragma unroll
            for (int nt = 0; nt < 8; nt++)
#pragma unroll
                for (int e = 0; e < 4; e++)
                    s[nt][e] *= 0.125f;
        }

        // ---- online softmax on fragments ----
        float mx0 = -1e30f, mx1 = -1e30f;
#pragma unroll
        for (int nt = 0; nt < 8; nt++) {
            mx0 = fmaxf(mx0, fmaxf(s[nt][0], s[nt][1]));
            mx1 = fmaxf(mx1, fmaxf(s[nt][2], s[nt][3]));
        }
        mx0 = fmaxf(mx0, __shfl_xor_sync(0xffffffffu, mx0, 1));
        mx0 = fmaxf(mx0, __shfl_xor_sync(0xffffffffu, mx0, 2));
        mx1 = fmaxf(mx1, __shfl_xor_sync(0xffffffffu, mx1, 1));
        mx1 = fmaxf(mx1, __shfl_xor_sync(0xffffffffu, mx1, 2));

        float mn0 = fmaxf(m0, mx0), mn1 = fmaxf(m1, mx1);
        float a0 = __expf(m0 - mn0), a1 = __expf(m1 - mn1);
        float sum0 = 0.f, sum1 = 0.f;
#pragma unroll
        for (int nt = 0; nt < 8; nt++) {
            float p0 = __expf(s[nt][0] - mn0);
            float p1 = __expf(s[nt][1] - mn0);
            float p2 = __expf(s[nt][2] - mn1);
            float p3 = __expf(s[nt][3] - mn1);
            s[nt][0] = p0; s[nt][1] = p1; s[nt][2] = p2; s[nt][3] = p3;
            sum0 += p0 + p1;
            sum1 += p2 + p3;
        }
        sum0 += __shfl_xor_sync(0xffffffffu, sum0, 1);
        sum0 += __shfl_xor_sync(0xffffffffu, sum0, 2);
        sum1 += __shfl_xor_sync(0xffffffffu, sum1, 1);
        sum1 += __shfl_xor_sync(0xffffffffu, sum1, 2);
        l0 = l0 * a0 + sum0;
        l1 = l1 * a1 + sum1;
        m0 = mn0; m1 = mn1;

        // ---- O rescale, skipped when all alphas are exactly 1 ----
        if (!__all_sync(0xffffffffu, (a0 == 1.f) && (a1 == 1.f))) {
#pragma unroll
            for (int i = 0; i < 8; i++) {
                o[i][0] *= a0; o[i][1] *= a0;
                o[i][2] *= a1; o[i][3] *= a1;
            }
        }

        // ---- repack P -> A fragments (cheap truncation split) ----
        uint32_t aPh[4][4], aPl[4][4];
#pragma unroll
        for (int ks = 0; ks < 4; ks++) {
#pragma unroll
            for (int half = 0; half < 2; half++) {
                int nt = 2 * ks + half;
                aPh[ks][half * 2]     = prmt_hi(s[nt][0], s[nt][1]);
                aPh[ks][half * 2 + 1] = prmt_hi(s[nt][2], s[nt][3]);
                aPl[ks][half * 2]     = cvtbf2(trunc_res(s[nt][0]),
                                               trunc_res(s[nt][1]));
                aPl[ks][half * 2 + 1] = cvtbf2(trunc_res(s[nt][2]),
                                               trunc_res(s[nt][3]));
            }
        }

        // ---- O += P @ V (3-term split) ----
#pragma unroll
        for (int ks = 0; ks < 4; ks++) {
            int rsel = (lane & 7) + (((lane >> 4) & 1) << 3);
            int c    = 2 * ks + ((lane >> 3) & 1);
#pragma unroll
            for (int p = 0; p < 4; p++) {
                uint32_t bh[4], bl[4];
                int row = p * 16 + rsel;
                uint32_t a = sVh + swz128(row, c);
                LDSM4(bh, a);
                LDSM4(bl, a + 8192);
#pragma unroll
                for (int sub = 0; sub < 2; sub++) {
                    int nt = p * 2 + sub, q = sub * 2;
                    MMA16816(o[nt], aPh[ks], bh[q], bh[q + 1]);
                    MMA16816(o[nt], aPh[ks], bl[q], bl[q + 1]);
                    MMA16816(o[nt], aPl[ks], bh[q], bh[q + 1]);
                }
            }
        }
        __syncthreads();
    }

    // ---- epilogue: O/l, split to bf16 hi/lo for GEMM2 ----
    float li0 = 1.f / l0, li1 = 1.f / l1;
    int r0 = qt * 128 + wrow + qr;
#pragma unroll
    for (int nt = 0; nt < 8; nt++) {
        int gcol = h * HD + nt * 8 + qc2;
        float f0 = o[nt][0] * li0, f1 = o[nt][1] * li0;
        float f2 = o[nt][2] * li1, f3 = o[nt][3] * li1;
        uint32_t hi0, lo0, hi1, lo1;
        split_pair(f0, f1, hi0, lo0);
        split_pair(f2, f3, hi1, lo1);
        size_t o0 = (size_t)r0 * KDIM + gcol;
        size_t o1 = (size_t)(r0 + 8) * KDIM + gcol;
        *(uint32_t*)(g_Ahi + o0) = hi0;
        *(uint32_t*)(g_Alo + o0) = lo0;
        *(uint32_t*)(g_Ahi + o1) = hi1;
        *(uint32_t*)(g_Alo + o1) = lo1;
    }
}

// ---------------- launch ------------------------------------------------------
extern "C" void kernel_launch(void* const* d_in, const int* in_sizes, int n_in,
                              void* d_out, int out_size)
{
    const float* x     = (const float*)d_in[0];
    const float* Wqkv  = (const float*)d_in[1];
    const float* bqkv  = (const float*)d_in[2];
    const float* Wproj = (const float*)d_in[3];
    const float* bproj = (const float*)d_in[4];
    float* out = (float*)d_out;

    __nv_bfloat16 *ahi, *alo, *bhi, *blo;
    cudaGetSymbolAddress((void**)&ahi, g_Ahi);
    cudaGetSymbolAddress((void**)&alo, g_Alo);
    cudaGetSymbolAddress((void**)&bhi, g_Bhi);
    cudaGetSymbolAddress((void**)&blo, g_Blo);

    cudaFuncSetAttribute(mma_gemm_kernel,
                         cudaFuncAttributeMaxDynamicSharedMemorySize, G_SMEM);
    cudaFuncSetAttribute(mma_gemm_qkv_kernel,
                         cudaFuncAttributeMaxDynamicSharedMemorySize, G_SMEM);
    cudaFuncSetAttribute(flash_mma_kernel,
                         cudaFuncAttributeMaxDynamicSharedMemorySize, FB_SMEM);

    init_invfreq_kernel<<<1, 32>>>();
    init_trig_kernel<<<(T_SEQ * 32) / 256, 256>>>();

    // ---- GEMM1 (fused RoPE/split epilogue): writes Qhi/Qlo/Khi/Klo + Vf ----
    split_kernel<<<(T_SEQ * (KDIM / 8)) / 256, 256>>>(x, ahi, alo,
                                                      T_SEQ * (KDIM / 8));
    transpose_split_kernel<<<dim3(3 * C_DIM / 32, KDIM / 32), 256>>>(
        Wqkv, bhi, blo, 3 * C_DIM);
    mma_gemm_qkv_kernel<<<dim3(3 * C_DIM / GBN, T_SEQ / GBM), 256, G_SMEM>>>(
        ahi, alo, bhi, blo, bqkv);

    // ---- V transpose + split ----
    v_split_kernel<<<dim3(T_SEQ / 64, NH), 256>>>();

    // ---- flash attention (epilogue writes GEMM2's A operand) ----
    flash_mma_kernel<<<dim3(T_SEQ / 128, NH), 256, FB_SMEM>>>();

    // ---- GEMM2: out = y @ Wproj + bproj ----
    transpose_split_kernel<<<dim3(C_DIM / 32, KDIM / 32), 256>>>(
        Wproj, bhi, blo, C_DIM);
    mma_gemm_kernel<<<dim3(C_DIM / GBN, T_SEQ / GBM), 256, G_SMEM>>>(
        ahi, alo, bhi, blo, bproj, out, C_DIM);
}

// round 17
// speedup vs baseline: 1.7303x; 1.0275x over previous
#include <cuda_runtime.h>
#include <cuda_bf16.h>
#include <math.h>
#include <stdint.h>

#define T_SEQ 4096
#define C_DIM 1024
#define NH    16
#define HD    64
#define KDIM  1024
// softmax scale folded into Q: 1/sqrt(64) * log2(e)
#define QSCALE 0.18033688011112042f

// ---------------- scratch (static device arrays, allowed) ---------------------
__device__ float g_Vf[(size_t)T_SEQ * C_DIM];   // fp32 V staging [t][h*64+d]
__device__ float g_invf[32];
__device__ float g_cos[(size_t)T_SEQ * 32];
__device__ float g_sin[(size_t)T_SEQ * 32];
// GEMM operands (bf16 split, row-major [rows][K])
__device__ __nv_bfloat16 g_Ahi[(size_t)T_SEQ * KDIM];
__device__ __nv_bfloat16 g_Alo[(size_t)T_SEQ * KDIM];
__device__ __nv_bfloat16 g_Bhi[(size_t)3 * C_DIM * KDIM];
__device__ __nv_bfloat16 g_Blo[(size_t)3 * C_DIM * KDIM];
// attention operands (bf16 split)
__device__ __nv_bfloat16 g_Qhi[(size_t)NH * T_SEQ * HD];   // [h][t][d], pre-scaled
__device__ __nv_bfloat16 g_Qlo[(size_t)NH * T_SEQ * HD];
__device__ __nv_bfloat16 g_Khi[(size_t)NH * T_SEQ * HD];
__device__ __nv_bfloat16 g_Klo[(size_t)NH * T_SEQ * HD];
__device__ __nv_bfloat16 g_Vthi[(size_t)NH * HD * T_SEQ];  // [h][d][t]
__device__ __nv_bfloat16 g_Vtlo[(size_t)NH * HD * T_SEQ];

// ---------------- helpers ------------------------------------------------------
__device__ __forceinline__ uint32_t smem_u32(const void* p) {
    uint32_t a;
    asm("{ .reg .u64 t; cvta.to.shared.u64 t, %1; cvt.u32.u64 %0, t; }"
        : "=r"(a) : "l"(p));
    return a;
}
__device__ __forceinline__ void cp16(uint32_t dst, const void* src) {
    asm volatile("cp.async.cg.shared.global [%0], [%1], 16;"
                 :: "r"(dst), "l"(src));
}
#define CP_COMMIT()  asm volatile("cp.async.commit_group;" ::: "memory")
#define CP_WAIT1()   asm volatile("cp.async.wait_group 1;" ::: "memory")
#define CP_WAITALL() asm volatile("cp.async.wait_all;" ::: "memory")

#define LDSM4(r, addr)                                                          \
    asm volatile("ldmatrix.sync.aligned.m8n8.x4.shared.b16 {%0,%1,%2,%3}, [%4];"\
                 : "=r"((r)[0]), "=r"((r)[1]), "=r"((r)[2]), "=r"((r)[3])       \
                 : "r"(addr))

#define MMA16816(c, a, b0, b1)                                                  \
    asm volatile("mma.sync.aligned.m16n8k16.row.col.f32.bf16.bf16.f32 "         \
                 "{%0,%1,%2,%3}, {%4,%5,%6,%7}, {%8,%9}, {%0,%1,%2,%3};"        \
                 : "+f"((c)[0]), "+f"((c)[1]), "+f"((c)[2]), "+f"((c)[3])       \
                 : "r"((a)[0]), "r"((a)[1]), "r"((a)[2]), "r"((a)[3]),          \
                   "r"(b0), "r"(b1))

// swizzle for [rows][64B] tiles (GEMM path)
__device__ __forceinline__ uint32_t swz(uint32_t row, uint32_t kb) {
    return row * 64u + (kb ^ (((row >> 1) & 3u) << 4));
}
// swizzle for [rows][128B] tiles (flash path), c = 16B-chunk index 0..7
__device__ __forceinline__ uint32_t swz128(uint32_t row, uint32_t c) {
    return row * 128u + ((c ^ (row & 7u)) << 4);
}
__device__ __forceinline__ uint32_t packbf(__nv_bfloat16 a, __nv_bfloat16 b) {
    __nv_bfloat162 t;
    t.x = a; t.y = b;
    return *reinterpret_cast<uint32_t*>(&t);
}
// pack truncated-bf16 of (a -> low half, b -> high half) in one PRMT
__device__ __forceinline__ uint32_t prmt_hi(float a, float b) {
    uint32_t r;
    asm("prmt.b32 %0, %1, %2, 0x7632;"
        : "=r"(r) : "r"(__float_as_uint(a)), "r"(__float_as_uint(b)));
    return r;
}
// packed rn cvt: x -> low bf16, y -> high bf16
__device__ __forceinline__ uint32_t cvtbf2(float x, float y) {
    uint32_t r;
    asm("cvt.rn.bf16x2.f32 %0, %1, %2;" : "=r"(r) : "f"(y), "f"(x));
    return r;
}
__device__ __forceinline__ float trunc_res(float p) {
    return p - __uint_as_float(__float_as_uint(p) & 0xFFFF0000u);
}
// base-2 exp (same HW op __expf lowers to, minus the log2e multiply)
__device__ __forceinline__ float ex2(float x) {
    float r;
    asm("ex2.approx.ftz.f32 %0, %1;" : "=f"(r) : "f"(x));
    return r;
}
// rn hi/lo split of a pair -> two packed words
__device__ __forceinline__ void split_pair(float a, float b,
                                           uint32_t& hi, uint32_t& lo) {
    __nv_bfloat16 ah = __float2bfloat16(a);
    __nv_bfloat16 bh = __float2bfloat16(b);
    hi = packbf(ah, bh);
    lo = packbf(__float2bfloat16(a - __bfloat162float(ah)),
                __float2bfloat16(b - __bfloat162float(bh)));
}

// ---------------- trig tables --------------------------------------------------
__global__ void init_invfreq_kernel() {
    int j = threadIdx.x;
    if (j < 32) {
        double e = (double)(2 * j) / 64.0;
        g_invf[j] = (float)exp(-e * log(10000.0));
    }
}

__device__ __forceinline__ float reduce_2pi(float theta) {
    double k = nearbyint((double)theta * 0.15915494309189535);
    return (float)((double)theta - k * 6.283185307179586);
}

__global__ void init_trig_kernel() {
    int idx = blockIdx.x * blockDim.x + threadIdx.x;
    if (idx >= T_SEQ * 32) return;
    int t = idx >> 5, j = idx & 31;
    float th = (float)t * g_invf[j];
    float r = reduce_2pi(th);
    float s, c;
    sincosf(r, &s, &c);
    g_cos[idx] = c;
    g_sin[idx] = s;
}

// ---------------- fp32 -> bf16 hi/lo split (row-major) -------------------------
__global__ void split_kernel(const float* __restrict__ src,
                             __nv_bfloat16* __restrict__ hi,
                             __nv_bfloat16* __restrict__ lo, int total) {
    int idx = blockIdx.x * blockDim.x + threadIdx.x;
    if (idx >= total) return;
    int m = idx >> 7;
    int k0 = (idx & 127) * 8;
    float4 a = *(const float4*)(src + (size_t)m * KDIM + k0);
    float4 b = *(const float4*)(src + (size_t)m * KDIM + k0 + 4);
    float v[8] = {a.x, a.y, a.z, a.w, b.x, b.y, b.z, b.w};
    __nv_bfloat16 h[8], l[8];
#pragma unroll
    for (int j = 0; j < 8; j++) {
        h[j] = __float2bfloat16(v[j]);
        l[j] = __float2bfloat16(v[j] - __bfloat162float(h[j]));
    }
    *(uint4*)(hi + (size_t)m * KDIM + k0) = *(uint4*)h;
    *(uint4*)(lo + (size_t)m * KDIM + k0) = *(uint4*)l;
}

// ---------------- W [K,N] -> Bt [N,K] bf16 hi/lo -------------------------------
__global__ void transpose_split_kernel(const float* __restrict__ W,
                                       __nv_bfloat16* __restrict__ hi,
                                       __nv_bfloat16* __restrict__ lo, int N) {
    __shared__ float s[32][33];
    int n0 = blockIdx.x * 32, k0 = blockIdx.y * 32;
    int t = threadIdx.x;
#pragma unroll
    for (int i = 0; i < 4; i++) {
        int e = t + i * 256;
        int kl = e >> 5, nl = e & 31;
        s[kl][nl] = W[(size_t)(k0 + kl) * N + n0 + nl];
    }
    __syncthreads();
    if (t < 128) {
        int nl = t >> 2, kg = t & 3, kl0 = kg * 8;
        int n = n0 + nl, k = k0 + kl0;
        __nv_bfloat16 h[8], l[8];
#pragma unroll
        for (int j = 0; j < 8; j++) {
            float v = s[kl0 + j][nl];
            h[j] = __float2bfloat16(v);
            l[j] = __float2bfloat16(v - __bfloat162float(h[j]));
        }
        *(uint4*)(hi + (size_t)n * KDIM + k) = *(uint4*)h;
        *(uint4*)(lo + (size_t)n * KDIM + k) = *(uint4*)l;
    }
}

// ---------------- shared GEMM mainloop (128x64, BK=32, 3-stage) ----------------
#define GBM 128
#define GBN 64
#define GBK 32
#define G_STAGES 3
#define G_STAGE_BYTES 24576   // Ahi 8K | Alo 8K | Bhi 4K | Blo 4K
#define G_SMEM (G_STAGES * G_STAGE_BYTES + 1024)

__device__ __forceinline__ void gemm_mainloop(
    const __nv_bfloat16* Ahi, const __nv_bfloat16* Alo,
    const __nv_bfloat16* Bhi, const __nv_bfloat16* Blo,
    int m0, int n0, uint32_t sb, int tid, int lane, int mw, int nw,
    float acc[2][4][4])
{
    const char* gA[2] = {(const char*)(Ahi + (size_t)m0 * KDIM),
                         (const char*)(Alo + (size_t)m0 * KDIM)};
    const char* gB[2] = {(const char*)(Bhi + (size_t)n0 * KDIM),
                         (const char*)(Blo + (size_t)n0 * KDIM)};

    int arow0 = tid >> 2,         akch0 = tid & 3;
    int arow1 = (tid + 256) >> 2, akch1 = tid & 3;
    int brow  = tid >> 2,         bkch  = tid & 3;

    auto load_stage = [&](int kc, int s) {
        uint32_t base = sb + (uint32_t)s * G_STAGE_BYTES;
        size_t gk = (size_t)kc * 64;
#pragma unroll
        for (int h = 0; h < 2; h++) {
            cp16(base + h * 8192 + swz(arow0, akch0 * 16),
                 gA[h] + (size_t)arow0 * (KDIM * 2) + gk + akch0 * 16);
            cp16(base + h * 8192 + swz(arow1, akch1 * 16),
                 gA[h] + (size_t)arow1 * (KDIM * 2) + gk + akch1 * 16);
            cp16(base + 16384 + h * 4096 + swz(brow, bkch * 16),
                 gB[h] + (size_t)brow * (KDIM * 2) + gk + bkch * 16);
        }
        CP_COMMIT();
    };

    const int KITERS = KDIM / GBK;
    load_stage(0, 0);
    load_stage(1, 1);

    for (int kc = 0; kc < KITERS; kc++) {
        CP_WAIT1();
        __syncthreads();
        if (kc + 2 < KITERS) load_stage(kc + 2, (kc + 2) % G_STAGES);
        else CP_COMMIT();

        uint32_t sbase = sb + (uint32_t)(kc % G_STAGES) * G_STAGE_BYTES;
#pragma unroll
        for (int ks = 0; ks < 2; ks++) {
            uint32_t ah[2][4], al[2][4], bh[2][4], bl[2][4];
            int kbA = ks * 32 + ((lane >> 4) << 4);
#pragma unroll
            for (int mt = 0; mt < 2; mt++) {
                int row = mw + mt * 16 + (lane & 7) + (((lane >> 3) & 1) << 3);
                uint32_t a = sbase + swz(row, kbA);
                LDSM4(ah[mt], a);
                LDSM4(al[mt], a + 8192);
            }
            int kbB = ks * 32 + (((lane >> 3) & 1) << 4);
#pragma unroll
            for (int p = 0; p < 2; p++) {
                int row = nw + p * 16 + (lane & 7) + (((lane >> 4) & 1) << 3);
                uint32_t a = sbase + 16384 + swz(row, kbB);
                LDSM4(bh[p], a);
                LDSM4(bl[p], a + 4096);
            }
#pragma unroll
            for (int mt = 0; mt < 2; mt++)
#pragma unroll
                for (int nt = 0; nt < 4; nt++) {
                    int p = nt >> 1, q = (nt & 1) * 2;
                    MMA16816(acc[mt][nt], ah[mt], bh[p][q], bh[p][q + 1]);
                    MMA16816(acc[mt][nt], ah[mt], bl[p][q], bl[p][q + 1]);
                    MMA16816(acc[mt][nt], al[mt], bh[p][q], bh[p][q + 1]);
                }
        }
    }
    CP_WAITALL();
}

// ---------------- plain GEMM (used for proj) -----------------------------------
__global__ __launch_bounds__(256, 2)
void mma_gemm_kernel(const __nv_bfloat16* __restrict__ Ahi,
                     const __nv_bfloat16* __restrict__ Alo,
                     const __nv_bfloat16* __restrict__ Bhi,
                     const __nv_bfloat16* __restrict__ Blo,
                     const float* __restrict__ bias,
                     float* __restrict__ C, int N)
{
    extern __shared__ char sraw[];
    char* smp = (char*)(((uintptr_t)sraw + 1023) & ~(uintptr_t)1023);
    uint32_t sb = smem_u32(smp);

    int tid = threadIdx.x, lane = tid & 31, w = tid >> 5;
    int m0 = blockIdx.y * GBM, n0 = blockIdx.x * GBN;
    int mw = (w >> 1) * 32, nw = (w & 1) * 32;

    float acc[2][4][4];
#pragma unroll
    for (int i = 0; i < 2; i++)
#pragma unroll
        for (int j = 0; j < 4; j++)
#pragma unroll
            for (int k = 0; k < 4; k++) acc[i][j][k] = 0.f;

    gemm_mainloop(Ahi, Alo, Bhi, Blo, m0, n0, sb, tid, lane, mw, nw, acc);

#pragma unroll
    for (int mt = 0; mt < 2; mt++)
#pragma unroll
        for (int nt = 0; nt < 4; nt++) {
            int row = m0 + mw + mt * 16 + (lane >> 2);
            int col = n0 + nw + nt * 8 + 2 * (lane & 3);
            float b0 = bias[col], b1 = bias[col + 1];
            float2 v0 = make_float2(acc[mt][nt][0] + b0, acc[mt][nt][1] + b1);
            float2 v1 = make_float2(acc[mt][nt][2] + b0, acc[mt][nt][3] + b1);
            *(float2*)(C + (size_t)row * N + col)       = v0;
            *(float2*)(C + (size_t)(row + 8) * N + col) = v1;
        }
}

// ---------------- QKV GEMM with fused RoPE + scale + bf16-split epilogue -------
__global__ __launch_bounds__(256, 2)
void mma_gemm_qkv_kernel(const __nv_bfloat16* __restrict__ Ahi,
                         const __nv_bfloat16* __restrict__ Alo,
                         const __nv_bfloat16* __restrict__ Bhi,
                         const __nv_bfloat16* __restrict__ Blo,
                         const float* __restrict__ bias)
{
    extern __shared__ char sraw[];
    char* smp = (char*)(((uintptr_t)sraw + 1023) & ~(uintptr_t)1023);
    uint32_t sb = smem_u32(smp);

    int tid = threadIdx.x, lane = tid & 31, w = tid >> 5;
    int m0 = blockIdx.y * GBM, n0 = blockIdx.x * GBN;
    int mw = (w >> 1) * 32, nw = (w & 1) * 32;

    float acc[2][4][4];
#pragma unroll
    for (int i = 0; i < 2; i++)
#pragma unroll
        for (int j = 0; j < 4; j++)
#pragma unroll
            for (int k = 0; k < 4; k++) acc[i][j][k] = 0.f;

    gemm_mainloop(Ahi, Alo, Bhi, Blo, m0, n0, sb, tid, lane, mw, nw, acc);

    int region = n0 >> 10;   // 0 = Q, 1 = K, 2 = V (block-uniform)

#pragma unroll
    for (int mt = 0; mt < 2; mt++)
#pragma unroll
        for (int nt = 0; nt < 4; nt++) {
            int t   = m0 + mw + mt * 16 + (lane >> 2);
            int col = n0 + nw + nt * 8 + 2 * (lane & 3);
            float b0 = bias[col], b1 = bias[col + 1];
            float v0 = acc[mt][nt][0] + b0, v1 = acc[mt][nt][1] + b1; // row t
            float v2 = acc[mt][nt][2] + b0, v3 = acc[mt][nt][3] + b1; // row t+8

            if (region == 2) {
                int d = col - 2048;
                *(float2*)(g_Vf + (size_t)t * C_DIM + d)       = make_float2(v0, v1);
                *(float2*)(g_Vf + (size_t)(t + 8) * C_DIM + d) = make_float2(v2, v3);
            } else {
                int g = col & 1023;
                int hh = g >> 6, d0 = g & 63, j0 = d0 & 31;
                // row t
                float c0 = g_cos[(size_t)t * 32 + j0];
                float c1 = g_cos[(size_t)t * 32 + j0 + 1];
                float s0 = g_sin[(size_t)t * 32 + j0];
                float s1 = g_sin[(size_t)t * 32 + j0 + 1];
                float ra = v0 * c0 - v1 * s0, rb = v1 * c1 + v0 * s1;
                // row t+8
                float c0b = g_cos[(size_t)(t + 8) * 32 + j0];
                float c1b = g_cos[(size_t)(t + 8) * 32 + j0 + 1];
                float s0b = g_sin[(size_t)(t + 8) * 32 + j0];
                float s1b = g_sin[(size_t)(t + 8) * 32 + j0 + 1];
                float rc = v2 * c0b - v3 * s0b, rd = v3 * c1b + v2 * s1b;

                if (region == 0) {   // fold softmax scale * log2e into Q
                    ra *= QSCALE; rb *= QSCALE;
                    rc *= QSCALE; rd *= QSCALE;
                }

                uint32_t hi0, lo0, hi1, lo1;
                split_pair(ra, rb, hi0, lo0);
                split_pair(rc, rd, hi1, lo1);

                __nv_bfloat16* dh = (region == 0) ? g_Qhi : g_Khi;
                __nv_bfloat16* dl = (region == 0) ? g_Qlo : g_Klo;
                size_t o0 = ((size_t)hh * T_SEQ + t) * HD + d0;
                size_t o1 = ((size_t)hh * T_SEQ + t + 8) * HD + d0;
                *(uint32_t*)(dh + o0) = hi0;
                *(uint32_t*)(dl + o0) = lo0;
                *(uint32_t*)(dh + o1) = hi1;
                *(uint32_t*)(dl + o1) = lo1;
            }
        }
}

// ---------------- V transpose + bf16 split ([t][c] fp32 -> [h][d][t] bf16) -----
__global__ __launch_bounds__(256)
void v_split_kernel() {
    __shared__ float sV[64][65];
    int h = blockIdx.y, t0 = blockIdx.x * 64, tid = threadIdx.x;

    for (int e = tid; e < 2048; e += 256) {
        int tl = e >> 5, i = e & 31;
        int t = t0 + tl, d0 = 2 * i;
        float2 v = *(const float2*)(g_Vf + (size_t)t * C_DIM + h * HD + d0);
        sV[tl][d0]     = v.x;
        sV[tl][d0 + 1] = v.y;
    }
    __syncthreads();
    for (int e = tid; e < 2048; e += 256) {
        int d = e >> 5, tp = (e & 31) * 2;
        float v0 = sV[tp][d], v1 = sV[tp + 1][d];
        __nv_bfloat16 h0 = __float2bfloat16(v0);
        __nv_bfloat16 h1 = __float2bfloat16(v1);
        __nv_bfloat16 l0 = __float2bfloat16(v0 - __bfloat162float(h0));
        __nv_bfloat16 l1 = __float2bfloat16(v1 - __bfloat162float(h1));
        size_t dst = ((size_t)h * HD + d) * T_SEQ + t0 + tp;
        *(uint32_t*)(g_Vthi + dst) = packbf(h0, h1);
        *(uint32_t*)(g_Vtlo + dst) = packbf(l0, l1);
    }
}

// ---------------- Flash attention, base-2 softmax ------------------------------
// Br=128 (8 warps x 16 rows), Bc=64, 2-stage cp.async K/Vt tiles.
// Q pre-scaled by 0.125*log2e; softmax done in base 2 (ex2), no scale loop.
#define FB_STAGE 32768     // Khi 8K | Klo 8K | Vthi 8K | Vtlo 8K
#define FB_SMEM  (2 * FB_STAGE + 1024)

__global__ __launch_bounds__(256, 2)
void flash_mma_kernel() {
    extern __shared__ char sraw[];
    char* smp = (char*)(((uintptr_t)sraw + 127) & ~(uintptr_t)127);
    uint32_t sb = smem_u32(smp);

    int tid = threadIdx.x, lane = tid & 31, w = tid >> 5;
    int h  = blockIdx.y;
    int qt = (int)gridDim.x - 1 - (int)blockIdx.x;
    int wrow = w * 16;
    int qr = lane >> 2, qc2 = 2 * (lane & 3);

    // ---- preload Q fragments (hi/lo) from global ----
    uint32_t aQh[4][4], aQl[4][4];
    {
        const __nv_bfloat16* Qh =
            g_Qhi + ((size_t)h * T_SEQ + qt * 128 + wrow + qr) * HD;
        const __nv_bfloat16* Ql =
            g_Qlo + ((size_t)h * T_SEQ + qt * 128 + wrow + qr) * HD;
#pragma unroll
        for (int ks = 0; ks < 4; ks++) {
            int k0 = ks * 16 + qc2;
            aQh[ks][0] = *(const uint32_t*)(Qh + k0);
            aQh[ks][1] = *(const uint32_t*)(Qh + 8 * HD + k0);
            aQh[ks][2] = *(const uint32_t*)(Qh + k0 + 8);
            aQh[ks][3] = *(const uint32_t*)(Qh + 8 * HD + k0 + 8);
            aQl[ks][0] = *(const uint32_t*)(Ql + k0);
            aQl[ks][1] = *(const uint32_t*)(Ql + 8 * HD + k0);
            aQl[ks][2] = *(const uint32_t*)(Ql + k0 + 8);
            aQl[ks][3] = *(const uint32_t*)(Ql + 8 * HD + k0 + 8);
        }
    }

    float o[8][4];
#pragma unroll
    for (int i = 0; i < 8; i++)
#pragma unroll
        for (int j = 0; j < 4; j++) o[i][j] = 0.f;
    float m0 = -1e30f, m1 = -1e30f, l0 = 0.f, l1 = 0.f;

    int ntiles = 2 * qt + 2;

    int lrow = tid >> 2;       // 0..63
    int lc   = tid & 3;        // chunk 0..3 (+4)
    auto load_stage = [&](int j, int buf) {
        uint32_t base = sb + (uint32_t)buf * FB_STAGE;
        const char* kh = (const char*)g_Khi
            + ((size_t)h * T_SEQ + (size_t)j * 64 + lrow) * (HD * 2);
        const char* kl = (const char*)g_Klo
            + ((size_t)h * T_SEQ + (size_t)j * 64 + lrow) * (HD * 2);
        const char* vh = (const char*)g_Vthi
            + (((size_t)h * HD + lrow) * T_SEQ + (size_t)j * 64) * 2;
        const char* vl = (const char*)g_Vtlo
            + (((size_t)h * HD + lrow) * T_SEQ + (size_t)j * 64) * 2;
#pragma unroll
        for (int cc = lc; cc < 8; cc += 4) {
            uint32_t sw = swz128(lrow, cc);
            cp16(base + sw,         kh + cc * 16);
            cp16(base + 8192  + sw, kl + cc * 16);
            cp16(base + 16384 + sw, vh + cc * 16);
            cp16(base + 24576 + sw, vl + cc * 16);
        }
    };

    load_stage(0, 0);
    CP_COMMIT();

    for (int j = 0; j < ntiles; j++) {
        if (j + 1 < ntiles) load_stage(j + 1, (j + 1) & 1);
        CP_COMMIT();
        CP_WAIT1();
        __syncthreads();

        uint32_t st  = sb + (uint32_t)(j & 1) * FB_STAGE;
        uint32_t sKh = st, sVh = st + 16384;

        // ---- S = Q @ K^T (3-term split); S is pre-scaled (base-2 logits) ----
        float s[8][4];
#pragma unroll
        for (int i = 0; i < 8; i++)
#pragma unroll
            for (int jj = 0; jj < 4; jj++) s[i][jj] = 0.f;

#pragma unroll
        for (int ks = 0; ks < 4; ks++) {
            int rsel = (lane & 7) + (((lane >> 4) & 1) << 3);
            int c    = 2 * ks + ((lane >> 3) & 1);
#pragma unroll
            for (int p = 0; p < 4; p++) {
                uint32_t bh[4], bl[4];
                int row = p * 16 + rsel;
                uint32_t a = sKh + swz128(row, c);
                LDSM4(bh, a);
                LDSM4(bl, a + 8192);
#pragma unroll
                for (int sub = 0; sub < 2; sub++) {
                    int nt = p * 2 + sub, q = sub * 2;
                    MMA16816(s[nt], aQh[ks], bh[q], bh[q + 1]);
                    MMA16816(s[nt], aQh[ks], bl[q], bl[q + 1]);
                    MMA16816(s[nt], aQl[ks], bh[q], bh[q + 1]);
                }
            }
        }

        // ---- causal mask only (no scale — folded into Q) ----
        if (j >= 2 * qt) {
            int row0 = qt * 128 + wrow + qr;
#pragma unroll
            for (int nt = 0; nt < 8; nt++) {
                int cb = j * 64 + nt * 8 + qc2;
#pragma unroll
                for (int e = 0; e < 4; e++) {
                    int col = cb + (e & 1);
                    int row = row0 + (e >> 1) * 8;
                    if (col > row) s[nt][e] = -1e30f;
                }
            }
        }

        // ---- online softmax (base 2) on fragments ----
        float mx0 = -1e30f, mx1 = -1e30f;
#pragma unroll
        for (int nt = 0; nt < 8; nt++) {
            mx0 = fmaxf(mx0, fmaxf(s[nt][0], s[nt][1]));
            mx1 = fmaxf(mx1, fmaxf(s[nt][2], s[nt][3]));
        }
        mx0 = fmaxf(mx0, __shfl_xor_sync(0xffffffffu, mx0, 1));
        mx0 = fmaxf(mx0, __shfl_xor_sync(0xffffffffu, mx0, 2));
        mx1 = fmaxf(mx1, __shfl_xor_sync(0xffffffffu, mx1, 1));
        mx1 = fmaxf(mx1, __shfl_xor_sync(0xffffffffu, mx1, 2));

        float mn0 = fmaxf(m0, mx0), mn1 = fmaxf(m1, mx1);
        float a0 = ex2(m0 - mn0), a1 = ex2(m1 - mn1);
        float sum0 = 0.f, sum1 = 0.f;
#pragma unroll
        for (int nt = 0; nt < 8; nt++) {
            float p0 = ex2(s[nt][0] - mn0);
            float p1 = ex2(s[nt][1] - mn0);
            float p2 = ex2(s[nt][2] - mn1);
            float p3 = ex2(s[nt][3] - mn1);
            s[nt][0] = p0; s[nt][1] = p1; s[nt][2] = p2; s[nt][3] = p3;
            sum0 += p0 + p1;
            sum1 += p2 + p3;
        }
        sum0 += __shfl_xor_sync(0xffffffffu, sum0, 1);
        sum0 += __shfl_xor_sync(0xffffffffu, sum0, 2);
        sum1 += __shfl_xor_sync(0xffffffffu, sum1, 1);
        sum1 += __shfl_xor_sync(0xffffffffu, sum1, 2);
        l0 = l0 * a0 + sum0;
        l1 = l1 * a1 + sum1;
        m0 = mn0; m1 = mn1;

        // ---- O rescale, skipped when all alphas are exactly 1 ----
        if (!__all_sync(0xffffffffu, (a0 == 1.f) && (a1 == 1.f))) {
#pragma unroll
            for (int i = 0; i < 8; i++) {
                o[i][0] *= a0; o[i][1] *= a0;
                o[i][2] *= a1; o[i][3] *= a1;
            }
        }

        // ---- repack P -> A fragments (cheap truncation split) ----
        uint32_t aPh[4][4], aPl[4][4];
#pragma unroll
        for (int ks = 0; ks < 4; ks++) {
#pragma unroll
            for (int half = 0; half < 2; half++) {
                int nt = 2 * ks + half;
                aPh[ks][half * 2]     = prmt_hi(s[nt][0], s[nt][1]);
                aPh[ks][half * 2 + 1] = prmt_hi(s[nt][2], s[nt][3]);
                aPl[ks][half * 2]     = cvtbf2(trunc_res(s[nt][0]),
                                               trunc_res(s[nt][1]));
                aPl[ks][half * 2 + 1] = cvtbf2(trunc_res(s[nt][2]),
                                               trunc_res(s[nt][3]));
            }
        }

        // ---- O += P @ V (3-term split) ----
#pragma unroll
        for (int ks = 0; ks < 4; ks++) {
            int rsel = (lane & 7) + (((lane >> 4) & 1) << 3);
            int c    = 2 * ks + ((lane >> 3) & 1);
#pragma unroll
            for (int p = 0; p < 4; p++) {
                uint32_t bh[4], bl[4];
                int row = p * 16 + rsel;
                uint32_t a = sVh + swz128(row, c);
                LDSM4(bh, a);
                LDSM4(bl, a + 8192);
#pragma unroll
                for (int sub = 0; sub < 2; sub++) {
                    int nt = p * 2 + sub, q = sub * 2;
                    MMA16816(o[nt], aPh[ks], bh[q], bh[q + 1]);
                    MMA16816(o[nt], aPh[ks], bl[q], bl[q + 1]);
                    MMA16816(o[nt], aPl[ks], bh[q], bh[q + 1]);
                }
            }
        }
        __syncthreads();
    }

    // ---- epilogue: O/l, split to bf16 hi/lo for GEMM2 ----
    float li0 = 1.f / l0, li1 = 1.f / l1;
    int r0 = qt * 128 + wrow + qr;
#pragma unroll
    for (int nt = 0; nt < 8; nt++) {
        int gcol = h * HD + nt * 8 + qc2;
        float f0 = o[nt][0] * li0, f1 = o[nt][1] * li0;
        float f2 = o[nt][2] * li1, f3 = o[nt][3] * li1;
        uint32_t hi0, lo0, hi1, lo1;
        split_pair(f0, f1, hi0, lo0);
        split_pair(f2, f3, hi1, lo1);
        size_t o0 = (size_t)r0 * KDIM + gcol;
        size_t o1 = (size_t)(r0 + 8) * KDIM + gcol;
        *(uint32_t*)(g_Ahi + o0) = hi0;
        *(uint32_t*)(g_Alo + o0) = lo0;
        *(uint32_t*)(g_Ahi + o1) = hi1;
        *(uint32_t*)(g_Alo + o1) = lo1;
    }
}

// ---------------- launch ------------------------------------------------------
extern "C" void kernel_launch(void* const* d_in, const int* in_sizes, int n_in,
                              void* d_out, int out_size)
{
    const float* x     = (const float*)d_in[0];
    const float* Wqkv  = (const float*)d_in[1];
    const float* bqkv  = (const float*)d_in[2];
    const float* Wproj = (const float*)d_in[3];
    const float* bproj = (const float*)d_in[4];
    float* out = (float*)d_out;

    __nv_bfloat16 *ahi, *alo, *bhi, *blo;
    cudaGetSymbolAddress((void**)&ahi, g_Ahi);
    cudaGetSymbolAddress((void**)&alo, g_Alo);
    cudaGetSymbolAddress((void**)&bhi, g_Bhi);
    cudaGetSymbolAddress((void**)&blo, g_Blo);

    cudaFuncSetAttribute(mma_gemm_kernel,
                         cudaFuncAttributeMaxDynamicSharedMemorySize, G_SMEM);
    cudaFuncSetAttribute(mma_gemm_qkv_kernel,
                         cudaFuncAttributeMaxDynamicSharedMemorySize, G_SMEM);
    cudaFuncSetAttribute(flash_mma_kernel,
                         cudaFuncAttributeMaxDynamicSharedMemorySize, FB_SMEM);

    init_invfreq_kernel<<<1, 32>>>();
    init_trig_kernel<<<(T_SEQ * 32) / 256, 256>>>();

    // ---- GEMM1 (fused RoPE/scale/split epilogue) ----
    split_kernel<<<(T_SEQ * (KDIM / 8)) / 256, 256>>>(x, ahi, alo,
                                                      T_SEQ * (KDIM / 8));
    transpose_split_kernel<<<dim3(3 * C_DIM / 32, KDIM / 32), 256>>>(
        Wqkv, bhi, blo, 3 * C_DIM);
    mma_gemm_qkv_kernel<<<dim3(3 * C_DIM / GBN, T_SEQ / GBM), 256, G_SMEM>>>(
        ahi, alo, bhi, blo, bqkv);

    // ---- V transpose + split ----
    v_split_kernel<<<dim3(T_SEQ / 64, NH), 256>>>();

    // ---- flash attention (epilogue writes GEMM2's A operand) ----
    flash_mma_kernel<<<dim3(T_SEQ / 128, NH), 256, FB_SMEM>>>();

    // ---- GEMM2: out = y @ Wproj + bproj ----
    transpose_split_kernel<<<dim3(C_DIM / 32, KDIM / 32), 256>>>(
        Wproj, bhi, blo, C_DIM);
    mma_gemm_kernel<<<dim3(C_DIM / GBN, T_SEQ / GBM), 256, G_SMEM>>>(
        ahi, alo, bhi, blo, bproj, out, C_DIM);
}